// round 12
// baseline (speedup 1.0000x reference)
#include <cuda_runtime.h>
#include <cuda_bf16.h>
#include <math_constants.h>
#include <cstdint>

// Problem constants
#define NB 4
#define C_ 512
#define CI_ 256
#define N_ 4096
#define BN_ (NB * N_)

// ---------------------------------------------------------------------------
// Device scratch (allocation-free __device__ globals)
// ---------------------------------------------------------------------------
__device__ float g_gv   [BN_ * CI_];   // [b][k][o] fp32 (g projection)

__device__ __nv_bfloat16 g_xth[BN_ * C_], g_xtl[BN_ * C_];   // x^T hi/lo [b][n][c]
__device__ __nv_bfloat16 g_wh [3 * CI_ * C_], g_wl[3 * CI_ * C_]; // W concat [768][512]
__device__ __nv_bfloat16 g_woh[C_ * CI_], g_wol[C_ * CI_];   // w_out hi/lo [512][256]

__device__ __nv_bfloat16 g_th[BN_ * CI_], g_tl[BN_ * CI_];   // theta hi/lo [b][n][o]
__device__ __nv_bfloat16 g_fh[BN_ * CI_], g_fl[BN_ * CI_];   // phi hi/lo   [b][n][o]
__device__ __nv_bfloat16 g_gTh[NB * CI_ * N_], g_gTl[NB * CI_ * N_]; // g^T [b][o][k]
__device__ __nv_bfloat16 g_yh[BN_ * CI_], g_yl[BN_ * CI_];   // y hi/lo [b][n][o]

__device__ __nv_bfloat16 g_ph[(size_t)NB * N_ * N_];         // exp hi (128 MB)
__device__ __nv_bfloat16 g_pl[(size_t)NB * N_ * N_];         // exp lo (128 MB)
__device__ float g_lpart[(size_t)BN_ * 64];                  // row-sum partials
__device__ float g_rinv[BN_];                                // 1 / rowsum

// ---------------------------------------------------------------------------
// Baseline-PTX tensor helpers
// ---------------------------------------------------------------------------
__device__ __forceinline__ uint32_t smem_u32(const void* p) {
    uint32_t a;
    asm("{ .reg .u64 t; cvta.to.shared.u64 t, %1; cvt.u32.u64 %0, t; }"
        : "=r"(a) : "l"(p));
    return a;
}

__device__ __forceinline__ void ldsm4(uint32_t* r, uint32_t addr) {
    asm volatile("ldmatrix.sync.aligned.m8n8.x4.shared.b16 {%0,%1,%2,%3}, [%4];"
                 : "=r"(r[0]), "=r"(r[1]), "=r"(r[2]), "=r"(r[3]) : "r"(addr));
}

__device__ __forceinline__ void mma_bf(float* d, const uint32_t* a,
                                       uint32_t b0, uint32_t b1) {
    asm volatile(
        "mma.sync.aligned.m16n8k16.row.col.f32.bf16.bf16.f32 "
        "{%0,%1,%2,%3}, {%4,%5,%6,%7}, {%8,%9}, {%0,%1,%2,%3};"
        : "+f"(d[0]), "+f"(d[1]), "+f"(d[2]), "+f"(d[3])
        : "r"(a[0]), "r"(a[1]), "r"(a[2]), "r"(a[3]), "r"(b0), "r"(b1));
}

__device__ __forceinline__ void cpa16(uint32_t smem, const void* g) {
    asm volatile("cp.async.cg.shared.global [%0], [%1], 16;"
                 :: "r"(smem), "l"(g) : "memory");
}
#define CP_COMMIT() asm volatile("cp.async.commit_group;" ::: "memory")
#define CP_WAIT1()  asm volatile("cp.async.wait_group 1;" ::: "memory")
#define CP_WAIT0()  asm volatile("cp.async.wait_group 0;" ::: "memory")

__device__ __forceinline__ uint32_t pack_bf(float a, float b) {
    return ((uint32_t)__bfloat16_as_ushort(__float2bfloat16(b)) << 16) |
           (uint32_t)__bfloat16_as_ushort(__float2bfloat16(a));
}

// GEMM smem geometry: K-chunk = 64 bf16 (128 B) per row, pitch 144 B.
// 4 operand tiles (Ah, Al, Bh, Bl) x 128 rows per stage; 3 stages.
#define GP_BYTES   144
#define KCHUNK     64
#define TILE_BYTES (128 * GP_BYTES)       // 18432
#define BUF_BYTES  (4 * TILE_BYTES)       // 73728
#define GEMM_SMEM  (3 * BUF_BYTES)        // 221184

#define EXP_SHIFT 50.0f

// ---------------------------------------------------------------------------
// Kernel A: transpose + split x: [b][c][n] fp32 -> x^T hi/lo [b][n][c] bf16.
// ---------------------------------------------------------------------------
__global__ __launch_bounds__(256) void xtsplit_kernel(const float* __restrict__ x)
{
    __shared__ float tile[32][33];
    const int b  = blockIdx.z;
    const int n0 = blockIdx.x * 32;
    const int c0 = blockIdx.y * 32;
    const int tx = threadIdx.x & 31;
    const int ty = threadIdx.x >> 5;

    #pragma unroll
    for (int jj = 0; jj < 4; jj++) {
        int c = c0 + ty + 8 * jj;
        tile[ty + 8 * jj][tx] = x[(size_t)(b * C_ + c) * N_ + n0 + tx];
    }
    __syncthreads();
    #pragma unroll
    for (int jj = 0; jj < 4; jj++) {
        int n = n0 + ty + 8 * jj;
        float v = tile[tx][ty + 8 * jj];
        float h = __bfloat162float(__float2bfloat16(v));
        size_t di = (size_t)(b * N_ + n) * C_ + c0 + tx;
        g_xth[di] = __float2bfloat16(h);
        g_xtl[di] = __float2bfloat16(v - h);
    }
}

// ---------------------------------------------------------------------------
// Kernel B: split the three projection weight matrices into [768][512] hi/lo.
// ---------------------------------------------------------------------------
__global__ __launch_bounds__(256) void wsplit_kernel(
    const float* __restrict__ w_theta, const float* __restrict__ w_phi,
    const float* __restrict__ w_g)
{
    int i = blockIdx.x * 256 + threadIdx.x;
    int which = i >> 15;
    int loc   = i & 32767;
    const float* __restrict__ src =
        (which == 0) ? w_theta : (which == 1) ? w_phi : w_g;
    float4 v = ((const float4*)src)[loc];
    float vv[4] = {v.x, v.y, v.z, v.w};
    float h[4];
    #pragma unroll
    for (int j = 0; j < 4; j++) h[j] = __bfloat162float(__float2bfloat16(vv[j]));
    uint2 hp, lp;
    hp.x = pack_bf(h[0], h[1]);           hp.y = pack_bf(h[2], h[3]);
    lp.x = pack_bf(vv[0] - h[0], vv[1] - h[1]);
    lp.y = pack_bf(vv[2] - h[2], vv[3] - h[3]);
    ((uint2*)g_wh)[i] = hp;
    ((uint2*)g_wl)[i] = lp;
}

// ---------------------------------------------------------------------------
// Kernel B2: split w_out [512][256] into hi/lo.
// ---------------------------------------------------------------------------
__global__ __launch_bounds__(256) void wosplit_kernel(const float* __restrict__ w_out)
{
    int i = blockIdx.x * 256 + threadIdx.x;
    float4 v = ((const float4*)w_out)[i];
    float vv[4] = {v.x, v.y, v.z, v.w};
    float h[4];
    #pragma unroll
    for (int j = 0; j < 4; j++) h[j] = __bfloat162float(__float2bfloat16(vv[j]));
    uint2 hp, lp;
    hp.x = pack_bf(h[0], h[1]);           hp.y = pack_bf(h[2], h[3]);
    lp.x = pack_bf(vv[0] - h[0], vv[1] - h[1]);
    lp.y = pack_bf(vv[2] - h[2], vv[3] - h[3]);
    ((uint2*)g_woh)[i] = hp;
    ((uint2*)g_wol)[i] = lp;
}

// ---------------------------------------------------------------------------
// Load one 64-K chunk (4 tiles) into stage buffer `base`.
// lr = t>>3 (0..31), seg = t&7; rows lr + 32*i.
// ---------------------------------------------------------------------------
#define LOAD_CHUNK(base, A0, A1, B0, B1, ldA, ldB, rowA, rowB, ko)            \
    {                                                                         \
        _Pragma("unroll")                                                     \
        for (int i_ = 0; i_ < 4; i_++) {                                      \
            int r_ = lr + 32 * i_;                                            \
            size_t giA_ = (size_t)((rowA) + r_) * (ldA) + (ko) + seg * 8;     \
            size_t giB_ = (size_t)((rowB) + r_) * (ldB) + (ko) + seg * 8;     \
            uint32_t off_ = (uint32_t)r_ * GP_BYTES + seg * 16;               \
            cpa16((base) + 0 * TILE_BYTES + off_, (A0) + giA_);               \
            cpa16((base) + 1 * TILE_BYTES + off_, (A1) + giA_);               \
            cpa16((base) + 2 * TILE_BYTES + off_, (B0) + giB_);               \
            cpa16((base) + 3 * TILE_BYTES + off_, (B1) + giB_);               \
        }                                                                     \
    }

// MMA over one buffered 64-K chunk (4 k-steps of 16).
#define MMA_CHUNK(base)                                                        \
    {                                                                          \
        _Pragma("unroll")                                                      \
        for (int ks = 0; ks < 4; ks++) {                                       \
            uint32_t ah[2][4], al[2][4];                                       \
            _Pragma("unroll")                                                  \
            for (int wm = 0; wm < 2; wm++) {                                   \
                uint32_t aoff = (uint32_t)(warp_m * 32 + wm * 16 + (lane & 15)) * GP_BYTES \
                              + ks * 32 + (lane >> 4) * 16;                    \
                ldsm4(ah[wm], (base) + 0 * TILE_BYTES + aoff);                 \
                ldsm4(al[wm], (base) + 1 * TILE_BYTES + aoff);                 \
            }                                                                  \
            _Pragma("unroll")                                                  \
            for (int np = 0; np < 4; np++) {                                   \
                uint32_t boff = (uint32_t)(warp_n * 64 + np * 16 +             \
                                           ((lane >> 4) << 3) + (lane & 7)) * GP_BYTES \
                              + ks * 32 + ((lane >> 3) & 1) * 16;              \
                uint32_t bh[4], bl[4];                                         \
                ldsm4(bh, (base) + 2 * TILE_BYTES + boff);                     \
                ldsm4(bl, (base) + 3 * TILE_BYTES + boff);                     \
                _Pragma("unroll")                                              \
                for (int wm = 0; wm < 2; wm++) {                               \
                    mma_bf(acc[wm][2 * np],     ah[wm], bh[0], bh[1]);         \
                    mma_bf(acc[wm][2 * np],     ah[wm], bl[0], bl[1]);         \
                    mma_bf(acc[wm][2 * np],     al[wm], bh[0], bh[1]);         \
                    mma_bf(acc[wm][2 * np + 1], ah[wm], bh[2], bh[3]);         \
                    mma_bf(acc[wm][2 * np + 1], ah[wm], bl[2], bl[3]);         \
                    mma_bf(acc[wm][2 * np + 1], al[wm], bh[2], bh[3]);         \
                }                                                              \
            }                                                                  \
        }                                                                      \
    }

// 3-stage mainloop: one __syncthreads per chunk. Slot (kc+2)%3 was last read
// by MMA kc-1 (finished by every warp before this iteration's barrier).
#define GEMM_MAINLOOP(NCH, A0, A1, B0, B1, ldA, ldB, rowA, rowB)              \
    {                                                                         \
        LOAD_CHUNK(sb, A0, A1, B0, B1, ldA, ldB, rowA, rowB, 0);              \
        CP_COMMIT();                                                          \
        if ((NCH) > 1) {                                                      \
            LOAD_CHUNK(sb + BUF_BYTES, A0, A1, B0, B1, ldA, ldB,              \
                       rowA, rowB, KCHUNK);                                   \
            CP_COMMIT();                                                      \
        }                                                                     \
        for (int kc = 0; kc < (NCH); kc++) {                                  \
            if (kc + 2 < (NCH)) { CP_WAIT1(); } else { CP_WAIT0(); }          \
            __syncthreads();                                                  \
            if (kc + 2 < (NCH)) {                                             \
                LOAD_CHUNK(sb + ((kc + 2) % 3) * BUF_BYTES,                   \
                           A0, A1, B0, B1, ldA, ldB, rowA, rowB,              \
                           (kc + 2) * KCHUNK);                                \
                CP_COMMIT();                                                  \
            }                                                                 \
            MMA_CHUNK(sb + (kc % 3) * BUF_BYTES);                             \
        }                                                                     \
    }

// ---------------------------------------------------------------------------
// Kernel 1: projection GEMM (HMMA). C[m, j] = xT[m, :] . W[j, :] (K = 512)
// ---------------------------------------------------------------------------
__global__ __launch_bounds__(256, 1) void projmma_kernel(
    const float* __restrict__ b_theta, const float* __restrict__ b_phi,
    const float* __restrict__ b_g)
{
    extern __shared__ char sm[];
    const uint32_t sb = smem_u32(sm);
    const int t = threadIdx.x, lane = t & 31, wid = t >> 5;
    const int warp_m = wid >> 1, warp_n = wid & 1;
    const int m0 = blockIdx.x * 128, j0 = blockIdx.y * 128;

    float acc[2][8][4];
    #pragma unroll
    for (int i = 0; i < 2; i++)
        #pragma unroll
        for (int j = 0; j < 8; j++)
            #pragma unroll
            for (int k = 0; k < 4; k++) acc[i][j][k] = 0.0f;

    const int lr  = t >> 3;
    const int seg = t & 7;

    GEMM_MAINLOOP(8, g_xth, g_xtl, g_wh, g_wl, C_, C_, m0, j0);

    const int sel = j0 >> 8;
    const float* __restrict__ bias =
        (sel == 0) ? b_theta : (sel == 1) ? b_phi : b_g;

    #pragma unroll
    for (int wm = 0; wm < 2; wm++) {
        #pragma unroll
        for (int h = 0; h < 2; h++) {
            int row = m0 + warp_m * 32 + wm * 16 + (lane >> 2) + h * 8;
            #pragma unroll
            for (int nt = 0; nt < 8; nt++) {
                int col = j0 + warp_n * 64 + nt * 8 + (lane & 3) * 2;
                int jj  = col & 255;
                float v0 = acc[wm][nt][2 * h]     + bias[jj];
                float v1 = acc[wm][nt][2 * h + 1] + bias[jj + 1];
                size_t di = (size_t)row * 256 + jj;
                if (sel == 2) {
                    float2 f2; f2.x = v0; f2.y = v1;
                    *(float2*)&g_gv[di] = f2;
                } else {
                    float h0 = __bfloat162float(__float2bfloat16(v0));
                    float h1 = __bfloat162float(__float2bfloat16(v1));
                    uint32_t hp = pack_bf(h0, h1);
                    uint32_t lp = pack_bf(v0 - h0, v1 - h1);
                    if (sel == 0) {
                        *(uint32_t*)&g_th[di] = hp;
                        *(uint32_t*)&g_tl[di] = lp;
                    } else {
                        *(uint32_t*)&g_fh[di] = hp;
                        *(uint32_t*)&g_fl[di] = lp;
                    }
                }
            }
        }
    }
}

// ---------------------------------------------------------------------------
// Kernel 3: transpose + split g: [b][k][o] fp32 -> gT hi/lo [b][o][k] bf16.
// ---------------------------------------------------------------------------
__global__ __launch_bounds__(256) void tsplit_kernel()
{
    __shared__ float tile[32][33];
    const int b  = blockIdx.z;
    const int k0 = blockIdx.x * 32;
    const int o0 = blockIdx.y * 32;
    const int tx = threadIdx.x & 31;
    const int ty = threadIdx.x >> 5;

    #pragma unroll
    for (int jj = 0; jj < 4; jj++) {
        int k = k0 + ty + 8 * jj;
        tile[ty + 8 * jj][tx] = g_gv[(size_t)(b * N_ + k) * 256 + o0 + tx];
    }
    __syncthreads();
    #pragma unroll
    for (int jj = 0; jj < 4; jj++) {
        int o = o0 + ty + 8 * jj;
        float v = tile[tx][ty + 8 * jj];
        float h = __bfloat162float(__float2bfloat16(v));
        size_t di = (size_t)(b * 256 + o) * N_ + k0 + tx;
        g_gTh[di] = __float2bfloat16(h);
        g_gTl[di] = __float2bfloat16(v - h);
    }
}

// ---------------------------------------------------------------------------
// Kernel 4: GEMM-A + fused exp.  P = exp(theta . phi^T - 50) bf16 hi/lo.
// ---------------------------------------------------------------------------
__global__ __launch_bounds__(256, 1) void gemmA_kernel()
{
    extern __shared__ char sm[];
    const uint32_t sb = smem_u32(sm);
    const int t = threadIdx.x, lane = t & 31, wid = t >> 5;
    const int warp_m = wid >> 1, warp_n = wid & 1;
    const int m0 = blockIdx.x * 128, n0 = blockIdx.y * 128, b = blockIdx.z;

    float acc[2][8][4];
    #pragma unroll
    for (int i = 0; i < 2; i++)
        #pragma unroll
        for (int j = 0; j < 8; j++)
            #pragma unroll
            for (int k = 0; k < 4; k++) acc[i][j][k] = 0.0f;

    const int lr  = t >> 3;
    const int seg = t & 7;
    const int rA = b * N_ + m0, rB = b * N_ + n0;

    GEMM_MAINLOOP(4, g_th, g_tl, g_fh, g_fl, 256, 256, rA, rB);

    // fused exp epilogue
    #pragma unroll
    for (int wm = 0; wm < 2; wm++) {
        #pragma unroll
        for (int h = 0; h < 2; h++) {
            int row = m0 + warp_m * 32 + wm * 16 + (lane >> 2) + h * 8;
            __nv_bfloat16* __restrict__ PH =
                &g_ph[(size_t)(b * N_ + row) * N_ + n0 + warp_n * 64];
            __nv_bfloat16* __restrict__ PL =
                &g_pl[(size_t)(b * N_ + row) * N_ + n0 + warp_n * 64];
            float lsum = 0.0f;
            #pragma unroll
            for (int nt = 0; nt < 8; nt++) {
                float p0 = __expf(acc[wm][nt][2 * h]     - EXP_SHIFT);
                float p1 = __expf(acc[wm][nt][2 * h + 1] - EXP_SHIFT);
                lsum += p0 + p1;
                float h0 = __bfloat162float(__float2bfloat16(p0));
                float h1 = __bfloat162float(__float2bfloat16(p1));
                *(uint32_t*)&PH[nt * 8 + (lane & 3) * 2] = pack_bf(h0, h1);
                *(uint32_t*)&PL[nt * 8 + (lane & 3) * 2] = pack_bf(p0 - h0, p1 - h1);
            }
            lsum += __shfl_xor_sync(0xffffffffu, lsum, 1);
            lsum += __shfl_xor_sync(0xffffffffu, lsum, 2);
            if ((lane & 3) == 0)
                g_lpart[(size_t)(b * N_ + row) * 64 + blockIdx.y * 2 + warp_n] = lsum;
        }
    }
}

// ---------------------------------------------------------------------------
// Kernel 5: reduce row-sum partials -> 1/l. warp per row.
// ---------------------------------------------------------------------------
__global__ __launch_bounds__(256) void lsum_kernel()
{
    const int w = threadIdx.x >> 5, lane = threadIdx.x & 31;
    const int gr = blockIdx.x * 8 + w;
    float s = g_lpart[(size_t)gr * 64 + lane] + g_lpart[(size_t)gr * 64 + lane + 32];
    #pragma unroll
    for (int off = 16; off > 0; off >>= 1)
        s += __shfl_xor_sync(0xffffffffu, s, off);
    if (lane == 0) g_rinv[gr] = 1.0f / s;
}

// ---------------------------------------------------------------------------
// Kernel 6: GEMM-C  Y = P . gT  (K = 4096); epilogue writes y bf16 hi/lo.
// ---------------------------------------------------------------------------
__global__ __launch_bounds__(256, 1) void gemmC_kernel()
{
    extern __shared__ char sm[];
    const uint32_t sb = smem_u32(sm);
    const int t = threadIdx.x, lane = t & 31, wid = t >> 5;
    const int warp_m = wid >> 1, warp_n = wid & 1;
    const int m0 = blockIdx.x * 128, n0 = blockIdx.y * 128, b = blockIdx.z;

    float acc[2][8][4];
    #pragma unroll
    for (int i = 0; i < 2; i++)
        #pragma unroll
        for (int j = 0; j < 8; j++)
            #pragma unroll
            for (int k = 0; k < 4; k++) acc[i][j][k] = 0.0f;

    const int lr  = t >> 3;
    const int seg = t & 7;
    const int rA = b * N_ + m0, rB = b * 256 + n0;

    GEMM_MAINLOOP(64, g_ph, g_pl, g_gTh, g_gTl, (size_t)N_, (size_t)N_, rA, rB);

    #pragma unroll
    for (int wm = 0; wm < 2; wm++) {
        #pragma unroll
        for (int h = 0; h < 2; h++) {
            int row = m0 + warp_m * 32 + wm * 16 + (lane >> 2) + h * 8;
            float ri = g_rinv[b * N_ + row];
            size_t dbase = (size_t)(b * N_ + row) * 256 + n0 + warp_n * 64;
            #pragma unroll
            for (int nt = 0; nt < 8; nt++) {
                float v0 = acc[wm][nt][2 * h]     * ri;
                float v1 = acc[wm][nt][2 * h + 1] * ri;
                float h0 = __bfloat162float(__float2bfloat16(v0));
                float h1 = __bfloat162float(__float2bfloat16(v1));
                size_t di = dbase + nt * 8 + (lane & 3) * 2;
                *(uint32_t*)&g_yh[di] = pack_bf(h0, h1);
                *(uint32_t*)&g_yl[di] = pack_bf(v0 - h0, v1 - h1);
            }
        }
    }
}

// ---------------------------------------------------------------------------
// Kernel 7: output projection (HMMA) + bias + residual.
// ---------------------------------------------------------------------------
__global__ __launch_bounds__(256, 1) void outprojmma_kernel(
    const float* __restrict__ x, const float* __restrict__ b_out,
    float* __restrict__ out)
{
    extern __shared__ char sm[];
    const uint32_t sb = smem_u32(sm);
    const int t = threadIdx.x, lane = t & 31, wid = t >> 5;
    const int warp_m = wid >> 1, warp_n = wid & 1;
    const int m0 = blockIdx.x * 128, j0 = blockIdx.y * 128;

    float acc[2][8][4];
    #pragma unroll
    for (int i = 0; i < 2; i++)
        #pragma unroll
        for (int j = 0; j < 8; j++)
            #pragma unroll
            for (int k = 0; k < 4; k++) acc[i][j][k] = 0.0f;

    const int lr  = t >> 3;
    const int seg = t & 7;

    GEMM_MAINLOOP(4, g_yh, g_yl, g_woh, g_wol, 256, 256, m0, j0);

    __syncthreads();   // all warps done reading stage buffers before smemT reuse

    // stage transposed tile in smem: smemT[c_local][n_local], pitch 132 floats
    float* smemT = (float*)sm;
    #pragma unroll
    for (int wm = 0; wm < 2; wm++) {
        #pragma unroll
        for (int h = 0; h < 2; h++) {
            int row_l = warp_m * 32 + wm * 16 + (lane >> 2) + h * 8;
            #pragma unroll
            for (int nt = 0; nt < 8; nt++) {
                int col_l = warp_n * 64 + nt * 8 + (lane & 3) * 2;
                smemT[col_l * 132 + row_l]       = acc[wm][nt][2 * h];
                smemT[(col_l + 1) * 132 + row_l] = acc[wm][nt][2 * h + 1];
            }
        }
    }
    __syncthreads();

    const int b   = m0 >> 12;
    const int nn0 = m0 & 4095;
    const int c_l  = t & 127;
    const int half = t >> 7;
    const int c = j0 + c_l;
    const float bo = b_out[c];
    const size_t obase = (size_t)(b * 512 + c) * 4096 + nn0 + half * 64;
    const float* sp = &smemT[c_l * 132 + half * 64];
    #pragma unroll
    for (int i = 0; i < 16; i++) {
        float4 xv = *(const float4*)&x[obase + i * 4];
        float4 o4;
        o4.x = sp[i * 4 + 0] + bo + xv.x;
        o4.y = sp[i * 4 + 1] + bo + xv.y;
        o4.z = sp[i * 4 + 2] + bo + xv.z;
        o4.w = sp[i * 4 + 3] + bo + xv.w;
        *(float4*)&out[obase + i * 4] = o4;
    }
}

// ---------------------------------------------------------------------------
extern "C" void kernel_launch(void* const* d_in, const int* in_sizes, int n_in,
                              void* d_out, int out_size)
{
    (void)in_sizes; (void)n_in; (void)out_size;
    const float* x       = (const float*)d_in[0];
    const float* w_theta = (const float*)d_in[1];
    const float* b_theta = (const float*)d_in[2];
    const float* w_phi   = (const float*)d_in[3];
    const float* b_phi   = (const float*)d_in[4];
    const float* w_g     = (const float*)d_in[5];
    const float* b_g     = (const float*)d_in[6];
    const float* w_out   = (const float*)d_in[7];
    const float* b_out   = (const float*)d_in[8];
    float* out = (float*)d_out;

    xtsplit_kernel<<<dim3(N_ / 32, C_ / 32, NB), 256>>>(x);
    wsplit_kernel<<<(3 * CI_ * C_ / 4) / 256, 256>>>(w_theta, w_phi, w_g);
    wosplit_kernel<<<(C_ * CI_ / 4) / 256, 256>>>(w_out);

    cudaFuncSetAttribute(projmma_kernel,
                         cudaFuncAttributeMaxDynamicSharedMemorySize, GEMM_SMEM);
    projmma_kernel<<<dim3(BN_ / 128, 6, 1), 256, GEMM_SMEM>>>(b_theta, b_phi, b_g);

    tsplit_kernel<<<dim3(N_ / 32, CI_ / 32, NB), 256>>>();

    cudaFuncSetAttribute(gemmA_kernel,
                         cudaFuncAttributeMaxDynamicSharedMemorySize, GEMM_SMEM);
    gemmA_kernel<<<dim3(N_ / 128, N_ / 128, NB), 256, GEMM_SMEM>>>();

    lsum_kernel<<<BN_ / 8, 256>>>();

    cudaFuncSetAttribute(gemmC_kernel,
                         cudaFuncAttributeMaxDynamicSharedMemorySize, GEMM_SMEM);
    gemmC_kernel<<<dim3(N_ / 128, CI_ / 128, NB), 256, GEMM_SMEM>>>();

    cudaFuncSetAttribute(outprojmma_kernel,
                         cudaFuncAttributeMaxDynamicSharedMemorySize, GEMM_SMEM);
    outprojmma_kernel<<<dim3(BN_ / 128, C_ / 128, 1), 256, GEMM_SMEM>>>(x, b_out, out);
}

// round 13
// speedup vs baseline: 1.8680x; 1.8680x over previous
#include <cuda_runtime.h>
#include <cuda_bf16.h>
#include <math_constants.h>
#include <cstdint>

// Problem constants
#define NB 4
#define C_ 512
#define CI_ 256
#define N_ 4096
#define BN_ (NB * N_)

// ---------------------------------------------------------------------------
// Device scratch (allocation-free __device__ globals)
// ---------------------------------------------------------------------------
__device__ float g_gv   [BN_ * CI_];   // [b][k][o] fp32 (g projection)

__device__ __nv_bfloat16 g_xth[BN_ * C_], g_xtl[BN_ * C_];   // x^T hi/lo [b][n][c]
__device__ __nv_bfloat16 g_wh [3 * CI_ * C_], g_wl[3 * CI_ * C_]; // W concat [768][512]
__device__ __nv_bfloat16 g_woh[C_ * CI_], g_wol[C_ * CI_];   // w_out hi/lo [512][256]

__device__ __nv_bfloat16 g_th[BN_ * CI_], g_tl[BN_ * CI_];   // theta hi/lo [b][n][o]
__device__ __nv_bfloat16 g_fh[BN_ * CI_], g_fl[BN_ * CI_];   // phi hi/lo   [b][n][o]
__device__ __nv_bfloat16 g_gTh[NB * CI_ * N_], g_gTl[NB * CI_ * N_]; // g^T [b][o][k]
__device__ __nv_bfloat16 g_yh[BN_ * CI_], g_yl[BN_ * CI_];   // y hi/lo [b][n][o]

__device__ __nv_bfloat16 g_ph[(size_t)NB * N_ * N_];         // exp hi (128 MB)
__device__ __nv_bfloat16 g_pl[(size_t)NB * N_ * N_];         // exp lo (128 MB)
__device__ float g_lpart[(size_t)BN_ * 64];                  // row-sum partials
__device__ float g_rinv[BN_];                                // 1 / rowsum

// ---------------------------------------------------------------------------
// Baseline-PTX tensor helpers
// ---------------------------------------------------------------------------
__device__ __forceinline__ uint32_t smem_u32(const void* p) {
    uint32_t a;
    asm("{ .reg .u64 t; cvta.to.shared.u64 t, %1; cvt.u32.u64 %0, t; }"
        : "=r"(a) : "l"(p));
    return a;
}

__device__ __forceinline__ void ldsm4(uint32_t* r, uint32_t addr) {
    asm volatile("ldmatrix.sync.aligned.m8n8.x4.shared.b16 {%0,%1,%2,%3}, [%4];"
                 : "=r"(r[0]), "=r"(r[1]), "=r"(r[2]), "=r"(r[3]) : "r"(addr));
}

__device__ __forceinline__ void mma_bf(float* d, const uint32_t* a,
                                       uint32_t b0, uint32_t b1) {
    asm volatile(
        "mma.sync.aligned.m16n8k16.row.col.f32.bf16.bf16.f32 "
        "{%0,%1,%2,%3}, {%4,%5,%6,%7}, {%8,%9}, {%0,%1,%2,%3};"
        : "+f"(d[0]), "+f"(d[1]), "+f"(d[2]), "+f"(d[3])
        : "r"(a[0]), "r"(a[1]), "r"(a[2]), "r"(a[3]), "r"(b0), "r"(b1));
}

__device__ __forceinline__ void cpa16(uint32_t smem, const void* g) {
    asm volatile("cp.async.cg.shared.global [%0], [%1], 16;"
                 :: "r"(smem), "l"(g) : "memory");
}
#define CP_COMMIT() asm volatile("cp.async.commit_group;" ::: "memory")
#define CP_WAIT1()  asm volatile("cp.async.wait_group 1;" ::: "memory")
#define CP_WAIT0()  asm volatile("cp.async.wait_group 0;" ::: "memory")

__device__ __forceinline__ uint32_t pack_bf(float a, float b) {
    return ((uint32_t)__bfloat16_as_ushort(__float2bfloat16(b)) << 16) |
           (uint32_t)__bfloat16_as_ushort(__float2bfloat16(a));
}

// GEMM smem geometry (Round-10 proven): K-chunk = 32 bf16 (64 B) per row,
// pitch 80 B (20 words: row starts hit word 20r mod 32 =
// {0,20,8,28,16,4,24,12} -> each ldmatrix phase covers all 32 banks once).
// 4 tiles (Ah, Al, Bh, Bl) x 128 rows, double buffered: 81920 B -> 2 CTAs/SM.
#define GP_BYTES   80
#define KCHUNK     32
#define TILE_BYTES (128 * GP_BYTES)       // 10240
#define BUF_BYTES  (4 * TILE_BYTES)       // 40960
#define GEMM_SMEM  (2 * BUF_BYTES)        // 81920

#define EXP_SHIFT 50.0f

// ---------------------------------------------------------------------------
// Kernel A: transpose + split x: [b][c][n] fp32 -> x^T hi/lo [b][n][c] bf16.
// ---------------------------------------------------------------------------
__global__ __launch_bounds__(256) void xtsplit_kernel(const float* __restrict__ x)
{
    __shared__ float tile[32][33];
    const int b  = blockIdx.z;
    const int n0 = blockIdx.x * 32;
    const int c0 = blockIdx.y * 32;
    const int tx = threadIdx.x & 31;
    const int ty = threadIdx.x >> 5;

    #pragma unroll
    for (int jj = 0; jj < 4; jj++) {
        int c = c0 + ty + 8 * jj;
        tile[ty + 8 * jj][tx] = x[(size_t)(b * C_ + c) * N_ + n0 + tx];
    }
    __syncthreads();
    #pragma unroll
    for (int jj = 0; jj < 4; jj++) {
        int n = n0 + ty + 8 * jj;
        float v = tile[tx][ty + 8 * jj];
        float h = __bfloat162float(__float2bfloat16(v));
        size_t di = (size_t)(b * N_ + n) * C_ + c0 + tx;
        g_xth[di] = __float2bfloat16(h);
        g_xtl[di] = __float2bfloat16(v - h);
    }
}

// ---------------------------------------------------------------------------
// Kernel B: split the three projection weight matrices into [768][512] hi/lo.
// ---------------------------------------------------------------------------
__global__ __launch_bounds__(256) void wsplit_kernel(
    const float* __restrict__ w_theta, const float* __restrict__ w_phi,
    const float* __restrict__ w_g)
{
    int i = blockIdx.x * 256 + threadIdx.x;
    int which = i >> 15;
    int loc   = i & 32767;
    const float* __restrict__ src =
        (which == 0) ? w_theta : (which == 1) ? w_phi : w_g;
    float4 v = ((const float4*)src)[loc];
    float vv[4] = {v.x, v.y, v.z, v.w};
    float h[4];
    #pragma unroll
    for (int j = 0; j < 4; j++) h[j] = __bfloat162float(__float2bfloat16(vv[j]));
    uint2 hp, lp;
    hp.x = pack_bf(h[0], h[1]);           hp.y = pack_bf(h[2], h[3]);
    lp.x = pack_bf(vv[0] - h[0], vv[1] - h[1]);
    lp.y = pack_bf(vv[2] - h[2], vv[3] - h[3]);
    ((uint2*)g_wh)[i] = hp;
    ((uint2*)g_wl)[i] = lp;
}

// ---------------------------------------------------------------------------
// Kernel B2: split w_out [512][256] into hi/lo.
// ---------------------------------------------------------------------------
__global__ __launch_bounds__(256) void wosplit_kernel(const float* __restrict__ w_out)
{
    int i = blockIdx.x * 256 + threadIdx.x;
    float4 v = ((const float4*)w_out)[i];
    float vv[4] = {v.x, v.y, v.z, v.w};
    float h[4];
    #pragma unroll
    for (int j = 0; j < 4; j++) h[j] = __bfloat162float(__float2bfloat16(vv[j]));
    uint2 hp, lp;
    hp.x = pack_bf(h[0], h[1]);           hp.y = pack_bf(h[2], h[3]);
    lp.x = pack_bf(vv[0] - h[0], vv[1] - h[1]);
    lp.y = pack_bf(vv[2] - h[2], vv[3] - h[3]);
    ((uint2*)g_woh)[i] = hp;
    ((uint2*)g_wol)[i] = lp;
}

// ---------------------------------------------------------------------------
// Shared GEMM load macro: one K-chunk (32 cols) of 4 tiles into buffer `base`.
// lr = t>>2 (0..63), seg = t&3; rows lr, lr+64.
// ---------------------------------------------------------------------------
#define LOAD_CHUNK(base, A0, A1, B0, B1, ldA, ldB, rowA, rowB, ko)            \
    {                                                                         \
        _Pragma("unroll")                                                     \
        for (int i_ = 0; i_ < 2; i_++) {                                      \
            int r_ = lr + 64 * i_;                                            \
            size_t giA_ = (size_t)((rowA) + r_) * (ldA) + (ko) + seg * 8;     \
            size_t giB_ = (size_t)((rowB) + r_) * (ldB) + (ko) + seg * 8;     \
            uint32_t off_ = (uint32_t)r_ * GP_BYTES + seg * 16;               \
            cpa16((base) + 0 * TILE_BYTES + off_, (A0) + giA_);               \
            cpa16((base) + 1 * TILE_BYTES + off_, (A1) + giA_);               \
            cpa16((base) + 2 * TILE_BYTES + off_, (B0) + giB_);               \
            cpa16((base) + 3 * TILE_BYTES + off_, (B1) + giB_);               \
        }                                                                     \
    }

// MMA over one buffered chunk (2 k-steps of 16).
// Stream-outermost order within each np group: hh x4, hl x4, lh x4 over
// {wm, n-half}. Same-accumulator reuse distance = 4 MMAs (was 1), covering
// HMMA RAW latency. Per-accumulator addition order unchanged (hh->hl->lh):
// numerics bit-identical to the distance-1 version.
#define MMA_CHUNK(base)                                                        \
    {                                                                          \
        _Pragma("unroll")                                                      \
        for (int ks = 0; ks < 2; ks++) {                                       \
            uint32_t ah[2][4], al[2][4];                                       \
            _Pragma("unroll")                                                  \
            for (int wm = 0; wm < 2; wm++) {                                   \
                uint32_t aoff = (uint32_t)(warp_m * 32 + wm * 16 + (lane & 15)) * GP_BYTES \
                              + ks * 32 + (lane >> 4) * 16;                    \
                ldsm4(ah[wm], (base) + 0 * TILE_BYTES + aoff);                 \
                ldsm4(al[wm], (base) + 1 * TILE_BYTES + aoff);                 \
            }                                                                  \
            _Pragma("unroll")                                                  \
            for (int np = 0; np < 4; np++) {                                   \
                uint32_t boff = (uint32_t)(warp_n * 64 + np * 16 +             \
                                           ((lane >> 4) << 3) + (lane & 7)) * GP_BYTES \
                              + ks * 32 + ((lane >> 3) & 1) * 16;              \
                uint32_t bh[4], bl[4];                                         \
                ldsm4(bh, (base) + 2 * TILE_BYTES + boff);                     \
                ldsm4(bl, (base) + 3 * TILE_BYTES + boff);                     \
                /* stream hh */                                                \
                mma_bf(acc[0][2 * np],     ah[0], bh[0], bh[1]);               \
                mma_bf(acc[0][2 * np + 1], ah[0], bh[2], bh[3]);               \
                mma_bf(acc[1][2 * np],     ah[1], bh[0], bh[1]);               \
                mma_bf(acc[1][2 * np + 1], ah[1], bh[2], bh[3]);               \
                /* stream hl */                                                \
                mma_bf(acc[0][2 * np],     ah[0], bl[0], bl[1]);               \
                mma_bf(acc[0][2 * np + 1], ah[0], bl[2], bl[3]);               \
                mma_bf(acc[1][2 * np],     ah[1], bl[0], bl[1]);               \
                mma_bf(acc[1][2 * np + 1], ah[1], bl[2], bl[3]);               \
                /* stream lh */                                                \
                mma_bf(acc[0][2 * np],     al[0], bh[0], bh[1]);               \
                mma_bf(acc[0][2 * np + 1], al[0], bh[2], bh[3]);               \
                mma_bf(acc[1][2 * np],     al[1], bh[0], bh[1]);               \
                mma_bf(acc[1][2 * np + 1], al[1], bh[2], bh[3]);               \
            }                                                                  \
        }                                                                      \
    }

// ---------------------------------------------------------------------------
// Kernel 1: projection GEMM (HMMA). C[m, j] = xT[m, :] . W[j, :] (K = 512)
// ---------------------------------------------------------------------------
__global__ __launch_bounds__(256, 2) void projmma_kernel(
    const float* __restrict__ b_theta, const float* __restrict__ b_phi,
    const float* __restrict__ b_g)
{
    extern __shared__ char sm[];
    const uint32_t sb = smem_u32(sm);
    const int t = threadIdx.x, lane = t & 31, wid = t >> 5;
    const int warp_m = wid >> 1, warp_n = wid & 1;
    const int m0 = blockIdx.x * 128, j0 = blockIdx.y * 128;

    float acc[2][8][4];
    #pragma unroll
    for (int i = 0; i < 2; i++)
        #pragma unroll
        for (int j = 0; j < 8; j++)
            #pragma unroll
            for (int k = 0; k < 4; k++) acc[i][j][k] = 0.0f;

    const int lr  = t >> 2;
    const int seg = t & 3;

    LOAD_CHUNK(sb, g_xth, g_xtl, g_wh, g_wl, C_, C_, m0, j0, 0);
    CP_COMMIT();

    const int NCH = C_ / KCHUNK;   // 16
    for (int kc = 0; kc < NCH; kc++) {
        const int buf = kc & 1;
        if (kc + 1 < NCH) {
            LOAD_CHUNK(sb + (buf ^ 1) * BUF_BYTES, g_xth, g_xtl, g_wh, g_wl,
                       C_, C_, m0, j0, (kc + 1) * KCHUNK);
            CP_COMMIT();
            CP_WAIT1();
        } else {
            CP_WAIT0();
        }
        __syncthreads();
        MMA_CHUNK(sb + buf * BUF_BYTES);
        __syncthreads();
    }

    const int sel = j0 >> 8;
    const float* __restrict__ bias =
        (sel == 0) ? b_theta : (sel == 1) ? b_phi : b_g;

    #pragma unroll
    for (int wm = 0; wm < 2; wm++) {
        #pragma unroll
        for (int h = 0; h < 2; h++) {
            int row = m0 + warp_m * 32 + wm * 16 + (lane >> 2) + h * 8;
            #pragma unroll
            for (int nt = 0; nt < 8; nt++) {
                int col = j0 + warp_n * 64 + nt * 8 + (lane & 3) * 2;
                int jj  = col & 255;
                float v0 = acc[wm][nt][2 * h]     + bias[jj];
                float v1 = acc[wm][nt][2 * h + 1] + bias[jj + 1];
                size_t di = (size_t)row * 256 + jj;
                if (sel == 2) {
                    float2 f2; f2.x = v0; f2.y = v1;
                    *(float2*)&g_gv[di] = f2;
                } else {
                    float h0 = __bfloat162float(__float2bfloat16(v0));
                    float h1 = __bfloat162float(__float2bfloat16(v1));
                    uint32_t hp = pack_bf(h0, h1);
                    uint32_t lp = pack_bf(v0 - h0, v1 - h1);
                    if (sel == 0) {
                        *(uint32_t*)&g_th[di] = hp;
                        *(uint32_t*)&g_tl[di] = lp;
                    } else {
                        *(uint32_t*)&g_fh[di] = hp;
                        *(uint32_t*)&g_fl[di] = lp;
                    }
                }
            }
        }
    }
}

// ---------------------------------------------------------------------------
// Kernel 3: transpose + split g: [b][k][o] fp32 -> gT hi/lo [b][o][k] bf16.
// ---------------------------------------------------------------------------
__global__ __launch_bounds__(256) void tsplit_kernel()
{
    __shared__ float tile[32][33];
    const int b  = blockIdx.z;
    const int k0 = blockIdx.x * 32;
    const int o0 = blockIdx.y * 32;
    const int tx = threadIdx.x & 31;
    const int ty = threadIdx.x >> 5;

    #pragma unroll
    for (int jj = 0; jj < 4; jj++) {
        int k = k0 + ty + 8 * jj;
        tile[ty + 8 * jj][tx] = g_gv[(size_t)(b * N_ + k) * 256 + o0 + tx];
    }
    __syncthreads();
    #pragma unroll
    for (int jj = 0; jj < 4; jj++) {
        int o = o0 + ty + 8 * jj;
        float v = tile[tx][ty + 8 * jj];
        float h = __bfloat162float(__float2bfloat16(v));
        size_t di = (size_t)(b * 256 + o) * N_ + k0 + tx;
        g_gTh[di] = __float2bfloat16(h);
        g_gTl[di] = __float2bfloat16(v - h);
    }
}

// ---------------------------------------------------------------------------
// Kernel 4: GEMM-A + fused exp.  P = exp(theta . phi^T - 50) bf16 hi/lo.
// ---------------------------------------------------------------------------
__global__ __launch_bounds__(256, 2) void gemmA_kernel()
{
    extern __shared__ char sm[];
    const uint32_t sb = smem_u32(sm);
    const int t = threadIdx.x, lane = t & 31, wid = t >> 5;
    const int warp_m = wid >> 1, warp_n = wid & 1;
    const int m0 = blockIdx.x * 128, n0 = blockIdx.y * 128, b = blockIdx.z;

    float acc[2][8][4];
    #pragma unroll
    for (int i = 0; i < 2; i++)
        #pragma unroll
        for (int j = 0; j < 8; j++)
            #pragma unroll
            for (int k = 0; k < 4; k++) acc[i][j][k] = 0.0f;

    const int lr  = t >> 2;
    const int seg = t & 3;
    const int rA = b * N_ + m0, rB = b * N_ + n0;

    LOAD_CHUNK(sb, g_th, g_tl, g_fh, g_fl, 256, 256, rA, rB, 0);
    CP_COMMIT();

    const int NCH = 256 / KCHUNK;   // 8
    for (int kc = 0; kc < NCH; kc++) {
        const int buf = kc & 1;
        if (kc + 1 < NCH) {
            LOAD_CHUNK(sb + (buf ^ 1) * BUF_BYTES, g_th, g_tl, g_fh, g_fl,
                       256, 256, rA, rB, (kc + 1) * KCHUNK);
            CP_COMMIT();
            CP_WAIT1();
        } else {
            CP_WAIT0();
        }
        __syncthreads();
        MMA_CHUNK(sb + buf * BUF_BYTES);
        __syncthreads();
    }

    // fused exp epilogue
    #pragma unroll
    for (int wm = 0; wm < 2; wm++) {
        #pragma unroll
        for (int h = 0; h < 2; h++) {
            int row = m0 + warp_m * 32 + wm * 16 + (lane >> 2) + h * 8;
            __nv_bfloat16* __restrict__ PH =
                &g_ph[(size_t)(b * N_ + row) * N_ + n0 + warp_n * 64];
            __nv_bfloat16* __restrict__ PL =
                &g_pl[(size_t)(b * N_ + row) * N_ + n0 + warp_n * 64];
            float lsum = 0.0f;
            #pragma unroll
            for (int nt = 0; nt < 8; nt++) {
                float p0 = __expf(acc[wm][nt][2 * h]     - EXP_SHIFT);
                float p1 = __expf(acc[wm][nt][2 * h + 1] - EXP_SHIFT);
                lsum += p0 + p1;
                float h0 = __bfloat162float(__float2bfloat16(p0));
                float h1 = __bfloat162float(__float2bfloat16(p1));
                *(uint32_t*)&PH[nt * 8 + (lane & 3) * 2] = pack_bf(h0, h1);
                *(uint32_t*)&PL[nt * 8 + (lane & 3) * 2] = pack_bf(p0 - h0, p1 - h1);
            }
            lsum += __shfl_xor_sync(0xffffffffu, lsum, 1);
            lsum += __shfl_xor_sync(0xffffffffu, lsum, 2);
            if ((lane & 3) == 0)
                g_lpart[(size_t)(b * N_ + row) * 64 + blockIdx.y * 2 + warp_n] = lsum;
        }
    }
}

// ---------------------------------------------------------------------------
// Kernel 5: reduce row-sum partials -> 1/l. warp per row.
// ---------------------------------------------------------------------------
__global__ __launch_bounds__(256) void lsum_kernel()
{
    const int w = threadIdx.x >> 5, lane = threadIdx.x & 31;
    const int gr = blockIdx.x * 8 + w;
    float s = g_lpart[(size_t)gr * 64 + lane] + g_lpart[(size_t)gr * 64 + lane + 32];
    #pragma unroll
    for (int off = 16; off > 0; off >>= 1)
        s += __shfl_xor_sync(0xffffffffu, s, off);
    if (lane == 0) g_rinv[gr] = 1.0f / s;
}

// ---------------------------------------------------------------------------
// Kernel 6: GEMM-C  Y = P . gT  (K = 4096); epilogue writes y bf16 hi/lo.
// ---------------------------------------------------------------------------
__global__ __launch_bounds__(256, 2) void gemmC_kernel()
{
    extern __shared__ char sm[];
    const uint32_t sb = smem_u32(sm);
    const int t = threadIdx.x, lane = t & 31, wid = t >> 5;
    const int warp_m = wid >> 1, warp_n = wid & 1;
    const int m0 = blockIdx.x * 128, n0 = blockIdx.y * 128, b = blockIdx.z;

    float acc[2][8][4];
    #pragma unroll
    for (int i = 0; i < 2; i++)
        #pragma unroll
        for (int j = 0; j < 8; j++)
            #pragma unroll
            for (int k = 0; k < 4; k++) acc[i][j][k] = 0.0f;

    const int lr  = t >> 2;
    const int seg = t & 3;
    const int rA = b * N_ + m0, rB = b * 256 + n0;

    LOAD_CHUNK(sb, g_ph, g_pl, g_gTh, g_gTl, (size_t)N_, (size_t)N_, rA, rB, 0);
    CP_COMMIT();

    const int NCH = N_ / KCHUNK;   // 128
    for (int kc = 0; kc < NCH; kc++) {
        const int buf = kc & 1;
        if (kc + 1 < NCH) {
            LOAD_CHUNK(sb + (buf ^ 1) * BUF_BYTES, g_ph, g_pl, g_gTh, g_gTl,
                       (size_t)N_, (size_t)N_, rA, rB, (kc + 1) * KCHUNK);
            CP_COMMIT();
            CP_WAIT1();
        } else {
            CP_WAIT0();
        }
        __syncthreads();
        MMA_CHUNK(sb + buf * BUF_BYTES);
        __syncthreads();
    }

    #pragma unroll
    for (int wm = 0; wm < 2; wm++) {
        #pragma unroll
        for (int h = 0; h < 2; h++) {
            int row = m0 + warp_m * 32 + wm * 16 + (lane >> 2) + h * 8;
            float ri = g_rinv[b * N_ + row];
            size_t dbase = (size_t)(b * N_ + row) * 256 + n0 + warp_n * 64;
            #pragma unroll
            for (int nt = 0; nt < 8; nt++) {
                float v0 = acc[wm][nt][2 * h]     * ri;
                float v1 = acc[wm][nt][2 * h + 1] * ri;
                float h0 = __bfloat162float(__float2bfloat16(v0));
                float h1 = __bfloat162float(__float2bfloat16(v1));
                size_t di = dbase + nt * 8 + (lane & 3) * 2;
                *(uint32_t*)&g_yh[di] = pack_bf(h0, h1);
                *(uint32_t*)&g_yl[di] = pack_bf(v0 - h0, v1 - h1);
            }
        }
    }
}

// ---------------------------------------------------------------------------
// Kernel 7: output projection (HMMA) + bias + residual.
// ---------------------------------------------------------------------------
__global__ __launch_bounds__(256, 2) void outprojmma_kernel(
    const float* __restrict__ x, const float* __restrict__ b_out,
    float* __restrict__ out)
{
    extern __shared__ char sm[];
    const uint32_t sb = smem_u32(sm);
    const int t = threadIdx.x, lane = t & 31, wid = t >> 5;
    const int warp_m = wid >> 1, warp_n = wid & 1;
    const int m0 = blockIdx.x * 128, j0 = blockIdx.y * 128;

    float acc[2][8][4];
    #pragma unroll
    for (int i = 0; i < 2; i++)
        #pragma unroll
        for (int j = 0; j < 8; j++)
            #pragma unroll
            for (int k = 0; k < 4; k++) acc[i][j][k] = 0.0f;

    const int lr  = t >> 2;
    const int seg = t & 3;

    LOAD_CHUNK(sb, g_yh, g_yl, g_woh, g_wol, 256, 256, m0, j0, 0);
    CP_COMMIT();

    const int NCH = 256 / KCHUNK;   // 8
    for (int kc = 0; kc < NCH; kc++) {
        const int buf = kc & 1;
        if (kc + 1 < NCH) {
            LOAD_CHUNK(sb + (buf ^ 1) * BUF_BYTES, g_yh, g_yl, g_woh, g_wol,
                       256, 256, m0, j0, (kc + 1) * KCHUNK);
            CP_COMMIT();
            CP_WAIT1();
        } else {
            CP_WAIT0();
        }
        __syncthreads();
        MMA_CHUNK(sb + buf * BUF_BYTES);
        __syncthreads();
    }

    // stage transposed tile in smem: smemT[c_local][n_local], pitch 132 floats
    // 128 * 132 * 4 = 67584 <= 81920 dynamic smem. Reuse gemm buffer space.
    float* smemT = (float*)sm;
    #pragma unroll
    for (int wm = 0; wm < 2; wm++) {
        #pragma unroll
        for (int h = 0; h < 2; h++) {
            int row_l = warp_m * 32 + wm * 16 + (lane >> 2) + h * 8;
            #pragma unroll
            for (int nt = 0; nt < 8; nt++) {
                int col_l = warp_n * 64 + nt * 8 + (lane & 3) * 2;
                smemT[col_l * 132 + row_l]       = acc[wm][nt][2 * h];
                smemT[(col_l + 1) * 132 + row_l] = acc[wm][nt][2 * h + 1];
            }
        }
    }
    __syncthreads();

    const int b   = m0 >> 12;
    const int nn0 = m0 & 4095;
    const int c_l  = t & 127;
    const int half = t >> 7;
    const int c = j0 + c_l;
    const float bo = b_out[c];
    const size_t obase = (size_t)(b * 512 + c) * 4096 + nn0 + half * 64;
    const float* sp = &smemT[c_l * 132 + half * 64];
    #pragma unroll
    for (int i = 0; i < 16; i++) {
        float4 xv = *(const float4*)&x[obase + i * 4];
        float4 o4;
        o4.x = sp[i * 4 + 0] + bo + xv.x;
        o4.y = sp[i * 4 + 1] + bo + xv.y;
        o4.z = sp[i * 4 + 2] + bo + xv.z;
        o4.w = sp[i * 4 + 3] + bo + xv.w;
        *(float4*)&out[obase + i * 4] = o4;
    }
}

// ---------------------------------------------------------------------------
extern "C" void kernel_launch(void* const* d_in, const int* in_sizes, int n_in,
                              void* d_out, int out_size)
{
    (void)in_sizes; (void)n_in; (void)out_size;
    const float* x       = (const float*)d_in[0];
    const float* w_theta = (const float*)d_in[1];
    const float* b_theta = (const float*)d_in[2];
    const float* w_phi   = (const float*)d_in[3];
    const float* b_phi   = (const float*)d_in[4];
    const float* w_g     = (const float*)d_in[5];
    const float* b_g     = (const float*)d_in[6];
    const float* w_out   = (const float*)d_in[7];
    const float* b_out   = (const float*)d_in[8];
    float* out = (float*)d_out;

    xtsplit_kernel<<<dim3(N_ / 32, C_ / 32, NB), 256>>>(x);
    wsplit_kernel<<<(3 * CI_ * C_ / 4) / 256, 256>>>(w_theta, w_phi, w_g);
    wosplit_kernel<<<(C_ * CI_ / 4) / 256, 256>>>(w_out);

    cudaFuncSetAttribute(projmma_kernel,
                         cudaFuncAttributeMaxDynamicSharedMemorySize, GEMM_SMEM);
    projmma_kernel<<<dim3(BN_ / 128, 6, 1), 256, GEMM_SMEM>>>(b_theta, b_phi, b_g);

    tsplit_kernel<<<dim3(N_ / 32, CI_ / 32, NB), 256>>>();

    cudaFuncSetAttribute(gemmA_kernel,
                         cudaFuncAttributeMaxDynamicSharedMemorySize, GEMM_SMEM);
    gemmA_kernel<<<dim3(N_ / 128, N_ / 128, NB), 256, GEMM_SMEM>>>();

    lsum_kernel<<<BN_ / 8, 256>>>();

    cudaFuncSetAttribute(gemmC_kernel,
                         cudaFuncAttributeMaxDynamicSharedMemorySize, GEMM_SMEM);
    gemmC_kernel<<<dim3(N_ / 128, CI_ / 128, NB), 256, GEMM_SMEM>>>();

    cudaFuncSetAttribute(outprojmma_kernel,
                         cudaFuncAttributeMaxDynamicSharedMemorySize, GEMM_SMEM);
    outprojmma_kernel<<<dim3(BN_ / 128, C_ / 128, 1), 256, GEMM_SMEM>>>(x, b_out, out);
}

// round 15
// speedup vs baseline: 2.0654x; 1.1057x over previous
#include <cuda_runtime.h>
#include <cuda_bf16.h>
#include <cuda_fp16.h>
#include <math_constants.h>
#include <cstdint>

// Problem constants
#define NB 4
#define C_ 512
#define CI_ 256
#define N_ 4096
#define BN_ (NB * N_)

// ---------------------------------------------------------------------------
// Device scratch (allocation-free __device__ globals)
// ---------------------------------------------------------------------------
__device__ float g_gv   [BN_ * CI_];   // [b][k][o] fp32 (g projection)

__device__ __half g_xh [BN_ * C_], g_xl[BN_ * C_];   // x^T fp16 pair [b][n][c]
__device__ __half g_wh [3 * CI_ * C_], g_wl[3 * CI_ * C_]; // W concat fp16 pair
__device__ __half g_woh[C_ * CI_], g_wol[C_ * CI_];  // w_out fp16 pair [512][256]

__device__ __half g_th[BN_ * CI_];                   // theta fp16 single [b][n][o]
__device__ __half g_fh[BN_ * CI_], g_fl[BN_ * CI_];  // phi fp16 pair
__device__ __nv_bfloat16 g_gTh[NB * CI_ * N_], g_gTl[NB * CI_ * N_]; // g^T bf16 pair
__device__ __half g_yh[BN_ * CI_];                   // y fp16 single [b][n][o]

__device__ __nv_bfloat16 g_ph[(size_t)NB * N_ * N_];         // exp hi (128 MB)
__device__ __nv_bfloat16 g_pl[(size_t)NB * N_ * N_];         // exp lo (128 MB)
__device__ float g_lpart[(size_t)BN_ * 64];                  // row-sum partials
__device__ float g_rinv[BN_];                                // 1 / rowsum

// ---------------------------------------------------------------------------
// Baseline-PTX tensor helpers
// ---------------------------------------------------------------------------
__device__ __forceinline__ uint32_t smem_u32(const void* p) {
    uint32_t a;
    asm("{ .reg .u64 t; cvta.to.shared.u64 t, %1; cvt.u32.u64 %0, t; }"
        : "=r"(a) : "l"(p));
    return a;
}

__device__ __forceinline__ void ldsm4(uint32_t* r, uint32_t addr) {
    asm volatile("ldmatrix.sync.aligned.m8n8.x4.shared.b16 {%0,%1,%2,%3}, [%4];"
                 : "=r"(r[0]), "=r"(r[1]), "=r"(r[2]), "=r"(r[3]) : "r"(addr));
}

__device__ __forceinline__ void mma_bf(float* d, const uint32_t* a,
                                       uint32_t b0, uint32_t b1) {
    asm volatile(
        "mma.sync.aligned.m16n8k16.row.col.f32.bf16.bf16.f32 "
        "{%0,%1,%2,%3}, {%4,%5,%6,%7}, {%8,%9}, {%0,%1,%2,%3};"
        : "+f"(d[0]), "+f"(d[1]), "+f"(d[2]), "+f"(d[3])
        : "r"(a[0]), "r"(a[1]), "r"(a[2]), "r"(a[3]), "r"(b0), "r"(b1));
}

__device__ __forceinline__ void mma_hf(float* d, const uint32_t* a,
                                       uint32_t b0, uint32_t b1) {
    asm volatile(
        "mma.sync.aligned.m16n8k16.row.col.f32.f16.f16.f32 "
        "{%0,%1,%2,%3}, {%4,%5,%6,%7}, {%8,%9}, {%0,%1,%2,%3};"
        : "+f"(d[0]), "+f"(d[1]), "+f"(d[2]), "+f"(d[3])
        : "r"(a[0]), "r"(a[1]), "r"(a[2]), "r"(a[3]), "r"(b0), "r"(b1));
}

__device__ __forceinline__ void cpa16(uint32_t smem, const void* g) {
    asm volatile("cp.async.cg.shared.global [%0], [%1], 16;"
                 :: "r"(smem), "l"(g) : "memory");
}
#define CP_COMMIT() asm volatile("cp.async.commit_group;" ::: "memory")
#define CP_WAIT1()  asm volatile("cp.async.wait_group 1;" ::: "memory")
#define CP_WAIT0()  asm volatile("cp.async.wait_group 0;" ::: "memory")

__device__ __forceinline__ uint32_t pack_bf(float a, float b) {
    return ((uint32_t)__bfloat16_as_ushort(__float2bfloat16(b)) << 16) |
           (uint32_t)__bfloat16_as_ushort(__float2bfloat16(a));
}
__device__ __forceinline__ uint32_t pack_hf(float a, float b) {
    return ((uint32_t)__half_as_ushort(__float2half_rn(b)) << 16) |
           (uint32_t)__half_as_ushort(__float2half_rn(a));
}

// smem geometry (R10 proven): K-chunk 32 half-words (64 B)/row, pitch 80 B
// (20-word pitch -> every ldmatrix phase covers all 32 banks once).
#define GP_BYTES   80
#define KCHUNK     32
#define TILE_BYTES (128 * GP_BYTES)       // 10240
#define BUF4_BYTES (4 * TILE_BYTES)       // 40960  (3-stream kernels)
#define SMEM4      (2 * BUF4_BYTES)       // 81920
#define BUF3_BYTES (3 * TILE_BYTES)       // 30720  (2-stream kernels)
#define SMEM3      (2 * BUF3_BYTES)       // 61440

#define EXP_SHIFT 50.0f

// ---------------------------------------------------------------------------
// Kernel A: transpose + split x: [b][c][n] fp32 -> x^T fp16 pair [b][n][c].
// ---------------------------------------------------------------------------
__global__ __launch_bounds__(256) void xtsplit_kernel(const float* __restrict__ x)
{
    __shared__ float tile[32][33];
    const int b  = blockIdx.z;
    const int n0 = blockIdx.x * 32;
    const int c0 = blockIdx.y * 32;
    const int tx = threadIdx.x & 31;
    const int ty = threadIdx.x >> 5;

    #pragma unroll
    for (int jj = 0; jj < 4; jj++) {
        int c = c0 + ty + 8 * jj;
        tile[ty + 8 * jj][tx] = x[(size_t)(b * C_ + c) * N_ + n0 + tx];
    }
    __syncthreads();
    #pragma unroll
    for (int jj = 0; jj < 4; jj++) {
        int n = n0 + ty + 8 * jj;
        float v = tile[tx][ty + 8 * jj];
        float h = __half2float(__float2half_rn(v));
        size_t di = (size_t)(b * N_ + n) * C_ + c0 + tx;
        g_xh[di] = __float2half_rn(h);
        g_xl[di] = __float2half_rn(v - h);
    }
}

// ---------------------------------------------------------------------------
// Kernel B: split the three projection weight matrices into fp16 hi/lo.
// ---------------------------------------------------------------------------
__global__ __launch_bounds__(256) void wsplit_kernel(
    const float* __restrict__ w_theta, const float* __restrict__ w_phi,
    const float* __restrict__ w_g)
{
    int i = blockIdx.x * 256 + threadIdx.x;
    int which = i >> 15;
    int loc   = i & 32767;
    const float* __restrict__ src =
        (which == 0) ? w_theta : (which == 1) ? w_phi : w_g;
    float4 v = ((const float4*)src)[loc];
    float vv[4] = {v.x, v.y, v.z, v.w};
    float h[4];
    #pragma unroll
    for (int j = 0; j < 4; j++) h[j] = __half2float(__float2half_rn(vv[j]));
    uint2 hp, lp;
    hp.x = pack_hf(h[0], h[1]);           hp.y = pack_hf(h[2], h[3]);
    lp.x = pack_hf(vv[0] - h[0], vv[1] - h[1]);
    lp.y = pack_hf(vv[2] - h[2], vv[3] - h[3]);
    ((uint2*)g_wh)[i] = hp;
    ((uint2*)g_wl)[i] = lp;
}

// ---------------------------------------------------------------------------
// Kernel B2: split w_out [512][256] into fp16 hi/lo.
// ---------------------------------------------------------------------------
__global__ __launch_bounds__(256) void wosplit_kernel(const float* __restrict__ w_out)
{
    int i = blockIdx.x * 256 + threadIdx.x;
    float4 v = ((const float4*)w_out)[i];
    float vv[4] = {v.x, v.y, v.z, v.w};
    float h[4];
    #pragma unroll
    for (int j = 0; j < 4; j++) h[j] = __half2float(__float2half_rn(vv[j]));
    uint2 hp, lp;
    hp.x = pack_hf(h[0], h[1]);           hp.y = pack_hf(h[2], h[3]);
    lp.x = pack_hf(vv[0] - h[0], vv[1] - h[1]);
    lp.y = pack_hf(vv[2] - h[2], vv[3] - h[3]);
    ((uint2*)g_woh)[i] = hp;
    ((uint2*)g_wol)[i] = lp;
}

// ---------------------------------------------------------------------------
// 4-tile load (3-stream path). lr = t>>2 (0..63), seg = t&3.
// ---------------------------------------------------------------------------
#define LOAD_CHUNK4(base, A0, A1, B0, B1, ldA, ldB, rowA, rowB, ko)           \
    {                                                                         \
        _Pragma("unroll")                                                     \
        for (int i_ = 0; i_ < 2; i_++) {                                      \
            int r_ = lr + 64 * i_;                                            \
            size_t giA_ = (size_t)((rowA) + r_) * (ldA) + (ko) + seg * 8;     \
            size_t giB_ = (size_t)((rowB) + r_) * (ldB) + (ko) + seg * 8;     \
            uint32_t off_ = (uint32_t)r_ * GP_BYTES + seg * 16;               \
            cpa16((base) + 0 * TILE_BYTES + off_, (A0) + giA_);               \
            cpa16((base) + 1 * TILE_BYTES + off_, (A1) + giA_);               \
            cpa16((base) + 2 * TILE_BYTES + off_, (B0) + giB_);               \
            cpa16((base) + 3 * TILE_BYTES + off_, (B1) + giB_);               \
        }                                                                     \
    }

// 3-tile load (2-stream path): A single + B pair.
#define LOAD_CHUNK3(base, A0, B0, B1, ldA, ldB, rowA, rowB, ko)               \
    {                                                                         \
        _Pragma("unroll")                                                     \
        for (int i_ = 0; i_ < 2; i_++) {                                      \
            int r_ = lr + 64 * i_;                                            \
            size_t giA_ = (size_t)((rowA) + r_) * (ldA) + (ko) + seg * 8;     \
            size_t giB_ = (size_t)((rowB) + r_) * (ldB) + (ko) + seg * 8;     \
            uint32_t off_ = (uint32_t)r_ * GP_BYTES + seg * 16;               \
            cpa16((base) + 0 * TILE_BYTES + off_, (A0) + giA_);               \
            cpa16((base) + 1 * TILE_BYTES + off_, (B0) + giB_);               \
            cpa16((base) + 2 * TILE_BYTES + off_, (B1) + giB_);               \
        }                                                                     \
    }

// 3-stream MMA (streams hh, hl, lh), parameterized on the MMA op.
#define MMA_CHUNK3S(base, MMAOP)                                               \
    {                                                                          \
        _Pragma("unroll")                                                      \
        for (int ks = 0; ks < 2; ks++) {                                       \
            uint32_t ah[2][4], al[2][4];                                       \
            _Pragma("unroll")                                                  \
            for (int wm = 0; wm < 2; wm++) {                                   \
                uint32_t aoff = (uint32_t)(warp_m * 32 + wm * 16 + (lane & 15)) * GP_BYTES \
                              + ks * 32 + (lane >> 4) * 16;                    \
                ldsm4(ah[wm], (base) + 0 * TILE_BYTES + aoff);                 \
                ldsm4(al[wm], (base) + 1 * TILE_BYTES + aoff);                 \
            }                                                                  \
            _Pragma("unroll")                                                  \
            for (int np = 0; np < 4; np++) {                                   \
                uint32_t boff = (uint32_t)(warp_n * 64 + np * 16 +             \
                                           ((lane >> 4) << 3) + (lane & 7)) * GP_BYTES \
                              + ks * 32 + ((lane >> 3) & 1) * 16;              \
                uint32_t bh[4], bl[4];                                         \
                ldsm4(bh, (base) + 2 * TILE_BYTES + boff);                     \
                ldsm4(bl, (base) + 3 * TILE_BYTES + boff);                     \
                MMAOP(acc[0][2 * np],     ah[0], bh[0], bh[1]);                \
                MMAOP(acc[0][2 * np + 1], ah[0], bh[2], bh[3]);                \
                MMAOP(acc[1][2 * np],     ah[1], bh[0], bh[1]);                \
                MMAOP(acc[1][2 * np + 1], ah[1], bh[2], bh[3]);                \
                MMAOP(acc[0][2 * np],     ah[0], bl[0], bl[1]);                \
                MMAOP(acc[0][2 * np + 1], ah[0], bl[2], bl[3]);                \
                MMAOP(acc[1][2 * np],     ah[1], bl[0], bl[1]);                \
                MMAOP(acc[1][2 * np + 1], ah[1], bl[2], bl[3]);                \
                MMAOP(acc[0][2 * np],     al[0], bh[0], bh[1]);                \
                MMAOP(acc[0][2 * np + 1], al[0], bh[2], bh[3]);                \
                MMAOP(acc[1][2 * np],     al[1], bh[0], bh[1]);                \
                MMAOP(acc[1][2 * np + 1], al[1], bh[2], bh[3]);                \
            }                                                                  \
        }                                                                      \
    }

// fp16 2-stream MMA: A single-word, B hi/lo pair.
#define MMA_CHUNK2S(base)                                                      \
    {                                                                          \
        _Pragma("unroll")                                                      \
        for (int ks = 0; ks < 2; ks++) {                                       \
            uint32_t ah[2][4];                                                 \
            _Pragma("unroll")                                                  \
            for (int wm = 0; wm < 2; wm++) {                                   \
                uint32_t aoff = (uint32_t)(warp_m * 32 + wm * 16 + (lane & 15)) * GP_BYTES \
                              + ks * 32 + (lane >> 4) * 16;                    \
                ldsm4(ah[wm], (base) + 0 * TILE_BYTES + aoff);                 \
            }                                                                  \
            _Pragma("unroll")                                                  \
            for (int np = 0; np < 4; np++) {                                   \
                uint32_t boff = (uint32_t)(warp_n * 64 + np * 16 +             \
                                           ((lane >> 4) << 3) + (lane & 7)) * GP_BYTES \
                              + ks * 32 + ((lane >> 3) & 1) * 16;              \
                uint32_t bh[4], bl[4];                                         \
                ldsm4(bh, (base) + 1 * TILE_BYTES + boff);                     \
                ldsm4(bl, (base) + 2 * TILE_BYTES + boff);                     \
                mma_hf(acc[0][2 * np],     ah[0], bh[0], bh[1]);               \
                mma_hf(acc[0][2 * np + 1], ah[0], bh[2], bh[3]);               \
                mma_hf(acc[1][2 * np],     ah[1], bh[0], bh[1]);               \
                mma_hf(acc[1][2 * np + 1], ah[1], bh[2], bh[3]);               \
                mma_hf(acc[0][2 * np],     ah[0], bl[0], bl[1]);               \
                mma_hf(acc[0][2 * np + 1], ah[0], bl[2], bl[3]);               \
                mma_hf(acc[1][2 * np],     ah[1], bl[0], bl[1]);               \
                mma_hf(acc[1][2 * np + 1], ah[1], bl[2], bl[3]);               \
            }                                                                  \
        }                                                                      \
    }

// ---------------------------------------------------------------------------
// Kernel 1: projection GEMM, fp16 3-stream (x pair . W pair, K = 512).
// Epilogue: theta fp16 single, phi fp16 pair, g fp32.
// ---------------------------------------------------------------------------
__global__ __launch_bounds__(256, 2) void projmma_kernel(
    const float* __restrict__ b_theta, const float* __restrict__ b_phi,
    const float* __restrict__ b_g)
{
    extern __shared__ char sm[];
    const uint32_t sb = smem_u32(sm);
    const int t = threadIdx.x, lane = t & 31, wid = t >> 5;
    const int warp_m = wid >> 1, warp_n = wid & 1;
    const int m0 = blockIdx.x * 128, j0 = blockIdx.y * 128;

    float acc[2][8][4];
    #pragma unroll
    for (int i = 0; i < 2; i++)
        #pragma unroll
        for (int j = 0; j < 8; j++)
            #pragma unroll
            for (int k = 0; k < 4; k++) acc[i][j][k] = 0.0f;

    const int lr  = t >> 2;
    const int seg = t & 3;

    LOAD_CHUNK4(sb, g_xh, g_xl, g_wh, g_wl, C_, C_, m0, j0, 0);
    CP_COMMIT();

    const int NCH = C_ / KCHUNK;   // 16
    for (int kc = 0; kc < NCH; kc++) {
        const int buf = kc & 1;
        if (kc + 1 < NCH) {
            LOAD_CHUNK4(sb + (buf ^ 1) * BUF4_BYTES, g_xh, g_xl, g_wh, g_wl,
                        C_, C_, m0, j0, (kc + 1) * KCHUNK);
            CP_COMMIT();
            CP_WAIT1();
        } else {
            CP_WAIT0();
        }
        __syncthreads();
        MMA_CHUNK3S(sb + buf * BUF4_BYTES, mma_hf);
        __syncthreads();
    }

    const int sel = j0 >> 8;
    const float* __restrict__ bias =
        (sel == 0) ? b_theta : (sel == 1) ? b_phi : b_g;

    #pragma unroll
    for (int wm = 0; wm < 2; wm++) {
        #pragma unroll
        for (int h = 0; h < 2; h++) {
            int row = m0 + warp_m * 32 + wm * 16 + (lane >> 2) + h * 8;
            #pragma unroll
            for (int nt = 0; nt < 8; nt++) {
                int col = j0 + warp_n * 64 + nt * 8 + (lane & 3) * 2;
                int jj  = col & 255;
                float v0 = acc[wm][nt][2 * h]     + bias[jj];
                float v1 = acc[wm][nt][2 * h + 1] + bias[jj + 1];
                size_t di = (size_t)row * 256 + jj;
                if (sel == 2) {
                    float2 f2; f2.x = v0; f2.y = v1;
                    *(float2*)&g_gv[di] = f2;
                } else if (sel == 0) {
                    *(uint32_t*)&g_th[di] = pack_hf(v0, v1);
                } else {
                    float h0 = __half2float(__float2half_rn(v0));
                    float h1 = __half2float(__float2half_rn(v1));
                    *(uint32_t*)&g_fh[di] = pack_hf(h0, h1);
                    *(uint32_t*)&g_fl[di] = pack_hf(v0 - h0, v1 - h1);
                }
            }
        }
    }
}

// ---------------------------------------------------------------------------
// Kernel 3: transpose + split g: [b][k][o] fp32 -> gT bf16 hi/lo [b][o][k].
// ---------------------------------------------------------------------------
__global__ __launch_bounds__(256) void tsplit_kernel()
{
    __shared__ float tile[32][33];
    const int b  = blockIdx.z;
    const int k0 = blockIdx.x * 32;
    const int o0 = blockIdx.y * 32;
    const int tx = threadIdx.x & 31;
    const int ty = threadIdx.x >> 5;

    #pragma unroll
    for (int jj = 0; jj < 4; jj++) {
        int k = k0 + ty + 8 * jj;
        tile[ty + 8 * jj][tx] = g_gv[(size_t)(b * N_ + k) * 256 + o0 + tx];
    }
    __syncthreads();
    #pragma unroll
    for (int jj = 0; jj < 4; jj++) {
        int o = o0 + ty + 8 * jj;
        float v = tile[tx][ty + 8 * jj];
        float h = __bfloat162float(__float2bfloat16(v));
        size_t di = (size_t)(b * 256 + o) * N_ + k0 + tx;
        g_gTh[di] = __float2bfloat16(h);
        g_gTl[di] = __float2bfloat16(v - h);
    }
}

// ---------------------------------------------------------------------------
// Kernel 4: GEMM-A (fp16 2-stream: theta single . phi pair) + fused exp.
// ---------------------------------------------------------------------------
__global__ __launch_bounds__(256, 2) void gemmA_kernel()
{
    extern __shared__ char sm[];
    const uint32_t sb = smem_u32(sm);
    const int t = threadIdx.x, lane = t & 31, wid = t >> 5;
    const int warp_m = wid >> 1, warp_n = wid & 1;
    const int m0 = blockIdx.x * 128, n0 = blockIdx.y * 128, b = blockIdx.z;

    float acc[2][8][4];
    #pragma unroll
    for (int i = 0; i < 2; i++)
        #pragma unroll
        for (int j = 0; j < 8; j++)
            #pragma unroll
            for (int k = 0; k < 4; k++) acc[i][j][k] = 0.0f;

    const int lr  = t >> 2;
    const int seg = t & 3;
    const int rA = b * N_ + m0, rB = b * N_ + n0;

    LOAD_CHUNK3(sb, g_th, g_fh, g_fl, 256, 256, rA, rB, 0);
    CP_COMMIT();

    const int NCH = 256 / KCHUNK;   // 8
    for (int kc = 0; kc < NCH; kc++) {
        const int buf = kc & 1;
        if (kc + 1 < NCH) {
            LOAD_CHUNK3(sb + (buf ^ 1) * BUF3_BYTES, g_th, g_fh, g_fl,
                        256, 256, rA, rB, (kc + 1) * KCHUNK);
            CP_COMMIT();
            CP_WAIT1();
        } else {
            CP_WAIT0();
        }
        __syncthreads();
        MMA_CHUNK2S(sb + buf * BUF3_BYTES);
        __syncthreads();
    }

    // fused exp epilogue
    #pragma unroll
    for (int wm = 0; wm < 2; wm++) {
        #pragma unroll
        for (int h = 0; h < 2; h++) {
            int row = m0 + warp_m * 32 + wm * 16 + (lane >> 2) + h * 8;
            __nv_bfloat16* __restrict__ PH =
                &g_ph[(size_t)(b * N_ + row) * N_ + n0 + warp_n * 64];
            __nv_bfloat16* __restrict__ PL =
                &g_pl[(size_t)(b * N_ + row) * N_ + n0 + warp_n * 64];
            float lsum = 0.0f;
            #pragma unroll
            for (int nt = 0; nt < 8; nt++) {
                float p0 = __expf(acc[wm][nt][2 * h]     - EXP_SHIFT);
                float p1 = __expf(acc[wm][nt][2 * h + 1] - EXP_SHIFT);
                lsum += p0 + p1;
                float h0 = __bfloat162float(__float2bfloat16(p0));
                float h1 = __bfloat162float(__float2bfloat16(p1));
                *(uint32_t*)&PH[nt * 8 + (lane & 3) * 2] = pack_bf(h0, h1);
                *(uint32_t*)&PL[nt * 8 + (lane & 3) * 2] = pack_bf(p0 - h0, p1 - h1);
            }
            lsum += __shfl_xor_sync(0xffffffffu, lsum, 1);
            lsum += __shfl_xor_sync(0xffffffffu, lsum, 2);
            if ((lane & 3) == 0)
                g_lpart[(size_t)(b * N_ + row) * 64 + blockIdx.y * 2 + warp_n] = lsum;
        }
    }
}

// ---------------------------------------------------------------------------
// Kernel 5: reduce row-sum partials -> 1/l.
// ---------------------------------------------------------------------------
__global__ __launch_bounds__(256) void lsum_kernel()
{
    const int w = threadIdx.x >> 5, lane = threadIdx.x & 31;
    const int gr = blockIdx.x * 8 + w;
    float s = g_lpart[(size_t)gr * 64 + lane] + g_lpart[(size_t)gr * 64 + lane + 32];
    #pragma unroll
    for (int off = 16; off > 0; off >>= 1)
        s += __shfl_xor_sync(0xffffffffu, s, off);
    if (lane == 0) g_rinv[gr] = 1.0f / s;
}

// ---------------------------------------------------------------------------
// Kernel 6: GEMM-C (bf16 3-stream). Y = P . gT (K = 4096); y -> fp16 single.
// ---------------------------------------------------------------------------
__global__ __launch_bounds__(256, 2) void gemmC_kernel()
{
    extern __shared__ char sm[];
    const uint32_t sb = smem_u32(sm);
    const int t = threadIdx.x, lane = t & 31, wid = t >> 5;
    const int warp_m = wid >> 1, warp_n = wid & 1;
    const int m0 = blockIdx.x * 128, n0 = blockIdx.y * 128, b = blockIdx.z;

    float acc[2][8][4];
    #pragma unroll
    for (int i = 0; i < 2; i++)
        #pragma unroll
        for (int j = 0; j < 8; j++)
            #pragma unroll
            for (int k = 0; k < 4; k++) acc[i][j][k] = 0.0f;

    const int lr  = t >> 2;
    const int seg = t & 3;
    const int rA = b * N_ + m0, rB = b * 256 + n0;

    LOAD_CHUNK4(sb, g_ph, g_pl, g_gTh, g_gTl, (size_t)N_, (size_t)N_, rA, rB, 0);
    CP_COMMIT();

    const int NCH = N_ / KCHUNK;   // 128
    for (int kc = 0; kc < NCH; kc++) {
        const int buf = kc & 1;
        if (kc + 1 < NCH) {
            LOAD_CHUNK4(sb + (buf ^ 1) * BUF4_BYTES, g_ph, g_pl, g_gTh, g_gTl,
                        (size_t)N_, (size_t)N_, rA, rB, (kc + 1) * KCHUNK);
            CP_COMMIT();
            CP_WAIT1();
        } else {
            CP_WAIT0();
        }
        __syncthreads();
        MMA_CHUNK3S(sb + buf * BUF4_BYTES, mma_bf);
        __syncthreads();
    }

    #pragma unroll
    for (int wm = 0; wm < 2; wm++) {
        #pragma unroll
        for (int h = 0; h < 2; h++) {
            int row = m0 + warp_m * 32 + wm * 16 + (lane >> 2) + h * 8;
            float ri = g_rinv[b * N_ + row];
            size_t dbase = (size_t)(b * N_ + row) * 256 + n0 + warp_n * 64;
            #pragma unroll
            for (int nt = 0; nt < 8; nt++) {
                float v0 = acc[wm][nt][2 * h]     * ri;
                float v1 = acc[wm][nt][2 * h + 1] * ri;
                size_t di = dbase + nt * 8 + (lane & 3) * 2;
                *(uint32_t*)&g_yh[di] = pack_hf(v0, v1);
            }
        }
    }
}

// ---------------------------------------------------------------------------
// Kernel 7: output projection (fp16 2-stream: y single . w_out pair)
// + bias + residual. K = 256.
// ---------------------------------------------------------------------------
__global__ __launch_bounds__(256, 2) void outprojmma_kernel(
    const float* __restrict__ x, const float* __restrict__ b_out,
    float* __restrict__ out)
{
    extern __shared__ char sm[];
    const uint32_t sb = smem_u32(sm);
    const int t = threadIdx.x, lane = t & 31, wid = t >> 5;
    const int warp_m = wid >> 1, warp_n = wid & 1;
    const int m0 = blockIdx.x * 128, j0 = blockIdx.y * 128;

    float acc[2][8][4];
    #pragma unroll
    for (int i = 0; i < 2; i++)
        #pragma unroll
        for (int j = 0; j < 8; j++)
            #pragma unroll
            for (int k = 0; k < 4; k++) acc[i][j][k] = 0.0f;

    const int lr  = t >> 2;
    const int seg = t & 3;

    LOAD_CHUNK3(sb, g_yh, g_woh, g_wol, 256, 256, m0, j0, 0);
    CP_COMMIT();

    const int NCH = 256 / KCHUNK;   // 8
    for (int kc = 0; kc < NCH; kc++) {
        const int buf = kc & 1;
        if (kc + 1 < NCH) {
            LOAD_CHUNK3(sb + (buf ^ 1) * BUF3_BYTES, g_yh, g_woh, g_wol,
                        256, 256, m0, j0, (kc + 1) * KCHUNK);
            CP_COMMIT();
            CP_WAIT1();
        } else {
            CP_WAIT0();
        }
        __syncthreads();
        MMA_CHUNK2S(sb + buf * BUF3_BYTES);
        __syncthreads();
    }

    // stage transposed tile: smemT[c_local][n_local], pitch 132 floats.
    // 128*132*4 = 67584 <= 81920 (SMEM4 alloc).
    float* smemT = (float*)sm;
    #pragma unroll
    for (int wm = 0; wm < 2; wm++) {
        #pragma unroll
        for (int h = 0; h < 2; h++) {
            int row_l = warp_m * 32 + wm * 16 + (lane >> 2) + h * 8;
            #pragma unroll
            for (int nt = 0; nt < 8; nt++) {
                int col_l = warp_n * 64 + nt * 8 + (lane & 3) * 2;
                smemT[col_l * 132 + row_l]       = acc[wm][nt][2 * h];
                smemT[(col_l + 1) * 132 + row_l] = acc[wm][nt][2 * h + 1];
            }
        }
    }
    __syncthreads();

    const int b   = m0 >> 12;
    const int nn0 = m0 & 4095;
    const int c_l  = t & 127;
    const int half = t >> 7;
    const int c = j0 + c_l;
    const float bo = b_out[c];
    const size_t obase = (size_t)(b * 512 + c) * 4096 + nn0 + half * 64;
    const float* sp = &smemT[c_l * 132 + half * 64];
    #pragma unroll
    for (int i = 0; i < 16; i++) {
        float4 xv = *(const float4*)&x[obase + i * 4];
        float4 o4;
        o4.x = sp[i * 4 + 0] + bo + xv.x;
        o4.y = sp[i * 4 + 1] + bo + xv.y;
        o4.z = sp[i * 4 + 2] + bo + xv.z;
        o4.w = sp[i * 4 + 3] + bo + xv.w;
        *(float4*)&out[obase + i * 4] = o4;
    }
}

// ---------------------------------------------------------------------------
extern "C" void kernel_launch(void* const* d_in, const int* in_sizes, int n_in,
                              void* d_out, int out_size)
{
    (void)in_sizes; (void)n_in; (void)out_size;
    const float* x       = (const float*)d_in[0];
    const float* w_theta = (const float*)d_in[1];
    const float* b_theta = (const float*)d_in[2];
    const float* w_phi   = (const float*)d_in[3];
    const float* b_phi   = (const float*)d_in[4];
    const float* w_g     = (const float*)d_in[5];
    const float* b_g     = (const float*)d_in[6];
    const float* w_out   = (const float*)d_in[7];
    const float* b_out   = (const float*)d_in[8];
    float* out = (float*)d_out;

    xtsplit_kernel<<<dim3(N_ / 32, C_ / 32, NB), 256>>>(x);
    wsplit_kernel<<<(3 * CI_ * C_ / 4) / 256, 256>>>(w_theta, w_phi, w_g);
    wosplit_kernel<<<(C_ * CI_ / 4) / 256, 256>>>(w_out);

    cudaFuncSetAttribute(projmma_kernel,
                         cudaFuncAttributeMaxDynamicSharedMemorySize, SMEM4);
    projmma_kernel<<<dim3(BN_ / 128, 6, 1), 256, SMEM4>>>(b_theta, b_phi, b_g);

    tsplit_kernel<<<dim3(N_ / 32, CI_ / 32, NB), 256>>>();

    cudaFuncSetAttribute(gemmA_kernel,
                         cudaFuncAttributeMaxDynamicSharedMemorySize, SMEM3);
    gemmA_kernel<<<dim3(N_ / 128, N_ / 128, NB), 256, SMEM3>>>();

    lsum_kernel<<<BN_ / 8, 256>>>();

    cudaFuncSetAttribute(gemmC_kernel,
                         cudaFuncAttributeMaxDynamicSharedMemorySize, SMEM4);
    gemmC_kernel<<<dim3(N_ / 128, CI_ / 128, NB), 256, SMEM4>>>();

    cudaFuncSetAttribute(outprojmma_kernel,
                         cudaFuncAttributeMaxDynamicSharedMemorySize, SMEM4);
    outprojmma_kernel<<<dim3(BN_ / 128, C_ / 128, 1), 256, SMEM4>>>(x, b_out, out);
}

// round 16
// speedup vs baseline: 2.3032x; 1.1151x over previous
#include <cuda_runtime.h>
#include <cuda_bf16.h>
#include <cuda_fp16.h>
#include <math_constants.h>
#include <cstdint>

// Problem constants
#define NB 4
#define C_ 512
#define CI_ 256
#define N_ 4096
#define BN_ (NB * N_)

// ---------------------------------------------------------------------------
// Device scratch (allocation-free __device__ globals)
// ---------------------------------------------------------------------------
__device__ float g_gv   [BN_ * CI_];   // [b][k][o] fp32 (g projection)

__device__ __half g_xh [BN_ * C_], g_xl[BN_ * C_];   // x^T fp16 pair [b][n][c]
__device__ __half g_wh [3 * CI_ * C_], g_wl[3 * CI_ * C_]; // W concat fp16 pair
__device__ __half g_woh[C_ * CI_], g_wol[C_ * CI_];  // w_out fp16 pair [512][256]

__device__ __half g_th[BN_ * CI_];                   // theta fp16 single [b][n][o]
__device__ __half g_fh[BN_ * CI_];                   // phi fp16 single
__device__ __nv_bfloat16 g_gTh[NB * CI_ * N_], g_gTl[NB * CI_ * N_]; // g^T bf16 pair
__device__ __half g_yh[BN_ * CI_];                   // y fp16 single [b][n][o]

__device__ __nv_bfloat16 g_ph[(size_t)NB * N_ * N_];         // exp hi (128 MB)
__device__ __nv_bfloat16 g_pl[(size_t)NB * N_ * N_];         // exp lo (128 MB)
__device__ float g_lpart[(size_t)BN_ * 64];                  // row-sum partials
__device__ float g_rinv[BN_];                                // 1 / rowsum

// ---------------------------------------------------------------------------
// Baseline-PTX tensor helpers
// ---------------------------------------------------------------------------
__device__ __forceinline__ uint32_t smem_u32(const void* p) {
    uint32_t a;
    asm("{ .reg .u64 t; cvta.to.shared.u64 t, %1; cvt.u32.u64 %0, t; }"
        : "=r"(a) : "l"(p));
    return a;
}

__device__ __forceinline__ void ldsm4(uint32_t* r, uint32_t addr) {
    asm volatile("ldmatrix.sync.aligned.m8n8.x4.shared.b16 {%0,%1,%2,%3}, [%4];"
                 : "=r"(r[0]), "=r"(r[1]), "=r"(r[2]), "=r"(r[3]) : "r"(addr));
}

__device__ __forceinline__ void mma_bf(float* d, const uint32_t* a,
                                       uint32_t b0, uint32_t b1) {
    asm volatile(
        "mma.sync.aligned.m16n8k16.row.col.f32.bf16.bf16.f32 "
        "{%0,%1,%2,%3}, {%4,%5,%6,%7}, {%8,%9}, {%0,%1,%2,%3};"
        : "+f"(d[0]), "+f"(d[1]), "+f"(d[2]), "+f"(d[3])
        : "r"(a[0]), "r"(a[1]), "r"(a[2]), "r"(a[3]), "r"(b0), "r"(b1));
}

__device__ __forceinline__ void mma_hf(float* d, const uint32_t* a,
                                       uint32_t b0, uint32_t b1) {
    asm volatile(
        "mma.sync.aligned.m16n8k16.row.col.f32.f16.f16.f32 "
        "{%0,%1,%2,%3}, {%4,%5,%6,%7}, {%8,%9}, {%0,%1,%2,%3};"
        : "+f"(d[0]), "+f"(d[1]), "+f"(d[2]), "+f"(d[3])
        : "r"(a[0]), "r"(a[1]), "r"(a[2]), "r"(a[3]), "r"(b0), "r"(b1));
}

__device__ __forceinline__ void cpa16(uint32_t smem, const void* g) {
    asm volatile("cp.async.cg.shared.global [%0], [%1], 16;"
                 :: "r"(smem), "l"(g) : "memory");
}
#define CP_COMMIT() asm volatile("cp.async.commit_group;" ::: "memory")
#define CP_WAIT1()  asm volatile("cp.async.wait_group 1;" ::: "memory")
#define CP_WAIT0()  asm volatile("cp.async.wait_group 0;" ::: "memory")

__device__ __forceinline__ uint32_t pack_bf(float a, float b) {
    return ((uint32_t)__bfloat16_as_ushort(__float2bfloat16(b)) << 16) |
           (uint32_t)__bfloat16_as_ushort(__float2bfloat16(a));
}
__device__ __forceinline__ uint32_t pack_hf(float a, float b) {
    return ((uint32_t)__half_as_ushort(__float2half_rn(b)) << 16) |
           (uint32_t)__half_as_ushort(__float2half_rn(a));
}

// smem geometry (R10 proven): K-chunk 32 half-words (64 B)/row, pitch 80 B
// (20-word pitch -> every ldmatrix phase covers all 32 banks once).
#define GP_BYTES   80
#define KCHUNK     32
#define TILE_BYTES (128 * GP_BYTES)       // 10240
#define BUF4_BYTES (4 * TILE_BYTES)       // 40960  (3-stream kernels)
#define SMEM4      (2 * BUF4_BYTES)       // 81920
#define BUF3_BYTES (3 * TILE_BYTES)       // 30720  (2-stream kernels)
#define SMEM3      (2 * BUF3_BYTES)       // 61440
#define BUF2_BYTES (2 * TILE_BYTES)       // 20480  (1-stream kernels)
#define SMEM2      (2 * BUF2_BYTES)       // 40960

#define EXP_SHIFT 50.0f

// ---------------------------------------------------------------------------
// Kernel A: transpose + split x: [b][c][n] fp32 -> x^T fp16 pair [b][n][c].
// ---------------------------------------------------------------------------
__global__ __launch_bounds__(256) void xtsplit_kernel(const float* __restrict__ x)
{
    __shared__ float tile[32][33];
    const int b  = blockIdx.z;
    const int n0 = blockIdx.x * 32;
    const int c0 = blockIdx.y * 32;
    const int tx = threadIdx.x & 31;
    const int ty = threadIdx.x >> 5;

    #pragma unroll
    for (int jj = 0; jj < 4; jj++) {
        int c = c0 + ty + 8 * jj;
        tile[ty + 8 * jj][tx] = x[(size_t)(b * C_ + c) * N_ + n0 + tx];
    }
    __syncthreads();
    #pragma unroll
    for (int jj = 0; jj < 4; jj++) {
        int n = n0 + ty + 8 * jj;
        float v = tile[tx][ty + 8 * jj];
        float h = __half2float(__float2half_rn(v));
        size_t di = (size_t)(b * N_ + n) * C_ + c0 + tx;
        g_xh[di] = __float2half_rn(h);
        g_xl[di] = __float2half_rn(v - h);
    }
}

// ---------------------------------------------------------------------------
// Kernel B: split the three projection weight matrices into fp16 hi/lo.
// ---------------------------------------------------------------------------
__global__ __launch_bounds__(256) void wsplit_kernel(
    const float* __restrict__ w_theta, const float* __restrict__ w_phi,
    const float* __restrict__ w_g)
{
    int i = blockIdx.x * 256 + threadIdx.x;
    int which = i >> 15;
    int loc   = i & 32767;
    const float* __restrict__ src =
        (which == 0) ? w_theta : (which == 1) ? w_phi : w_g;
    float4 v = ((const float4*)src)[loc];
    float vv[4] = {v.x, v.y, v.z, v.w};
    float h[4];
    #pragma unroll
    for (int j = 0; j < 4; j++) h[j] = __half2float(__float2half_rn(vv[j]));
    uint2 hp, lp;
    hp.x = pack_hf(h[0], h[1]);           hp.y = pack_hf(h[2], h[3]);
    lp.x = pack_hf(vv[0] - h[0], vv[1] - h[1]);
    lp.y = pack_hf(vv[2] - h[2], vv[3] - h[3]);
    ((uint2*)g_wh)[i] = hp;
    ((uint2*)g_wl)[i] = lp;
}

// ---------------------------------------------------------------------------
// Kernel B2: split w_out [512][256] into fp16 hi/lo.
// ---------------------------------------------------------------------------
__global__ __launch_bounds__(256) void wosplit_kernel(const float* __restrict__ w_out)
{
    int i = blockIdx.x * 256 + threadIdx.x;
    float4 v = ((const float4*)w_out)[i];
    float vv[4] = {v.x, v.y, v.z, v.w};
    float h[4];
    #pragma unroll
    for (int j = 0; j < 4; j++) h[j] = __half2float(__float2half_rn(vv[j]));
    uint2 hp, lp;
    hp.x = pack_hf(h[0], h[1]);           hp.y = pack_hf(h[2], h[3]);
    lp.x = pack_hf(vv[0] - h[0], vv[1] - h[1]);
    lp.y = pack_hf(vv[2] - h[2], vv[3] - h[3]);
    ((uint2*)g_woh)[i] = hp;
    ((uint2*)g_wol)[i] = lp;
}

// ---------------------------------------------------------------------------
// Loads. lr = t>>2 (0..63), seg = t&3.
// ---------------------------------------------------------------------------
#define LOAD_CHUNK4(base, A0, A1, B0, B1, ldA, ldB, rowA, rowB, ko)           \
    {                                                                         \
        _Pragma("unroll")                                                     \
        for (int i_ = 0; i_ < 2; i_++) {                                      \
            int r_ = lr + 64 * i_;                                            \
            size_t giA_ = (size_t)((rowA) + r_) * (ldA) + (ko) + seg * 8;     \
            size_t giB_ = (size_t)((rowB) + r_) * (ldB) + (ko) + seg * 8;     \
            uint32_t off_ = (uint32_t)r_ * GP_BYTES + seg * 16;               \
            cpa16((base) + 0 * TILE_BYTES + off_, (A0) + giA_);               \
            cpa16((base) + 1 * TILE_BYTES + off_, (A1) + giA_);               \
            cpa16((base) + 2 * TILE_BYTES + off_, (B0) + giB_);               \
            cpa16((base) + 3 * TILE_BYTES + off_, (B1) + giB_);               \
        }                                                                     \
    }

#define LOAD_CHUNK3(base, A0, B0, B1, ldA, ldB, rowA, rowB, ko)               \
    {                                                                         \
        _Pragma("unroll")                                                     \
        for (int i_ = 0; i_ < 2; i_++) {                                      \
            int r_ = lr + 64 * i_;                                            \
            size_t giA_ = (size_t)((rowA) + r_) * (ldA) + (ko) + seg * 8;     \
            size_t giB_ = (size_t)((rowB) + r_) * (ldB) + (ko) + seg * 8;     \
            uint32_t off_ = (uint32_t)r_ * GP_BYTES + seg * 16;               \
            cpa16((base) + 0 * TILE_BYTES + off_, (A0) + giA_);               \
            cpa16((base) + 1 * TILE_BYTES + off_, (B0) + giB_);               \
            cpa16((base) + 2 * TILE_BYTES + off_, (B1) + giB_);               \
        }                                                                     \
    }

#define LOAD_CHUNK2(base, A0, B0, ldA, ldB, rowA, rowB, ko)                   \
    {                                                                         \
        _Pragma("unroll")                                                     \
        for (int i_ = 0; i_ < 2; i_++) {                                      \
            int r_ = lr + 64 * i_;                                            \
            size_t giA_ = (size_t)((rowA) + r_) * (ldA) + (ko) + seg * 8;     \
            size_t giB_ = (size_t)((rowB) + r_) * (ldB) + (ko) + seg * 8;     \
            uint32_t off_ = (uint32_t)r_ * GP_BYTES + seg * 16;               \
            cpa16((base) + 0 * TILE_BYTES + off_, (A0) + giA_);               \
            cpa16((base) + 1 * TILE_BYTES + off_, (B0) + giB_);               \
        }                                                                     \
    }

// 3-stream MMA (hh, hl, lh), parameterized on MMA op.
#define MMA_CHUNK3S(base, MMAOP)                                               \
    {                                                                          \
        _Pragma("unroll")                                                      \
        for (int ks = 0; ks < 2; ks++) {                                       \
            uint32_t ah[2][4], al[2][4];                                       \
            _Pragma("unroll")                                                  \
            for (int wm = 0; wm < 2; wm++) {                                   \
                uint32_t aoff = (uint32_t)(warp_m * 32 + wm * 16 + (lane & 15)) * GP_BYTES \
                              + ks * 32 + (lane >> 4) * 16;                    \
                ldsm4(ah[wm], (base) + 0 * TILE_BYTES + aoff);                 \
                ldsm4(al[wm], (base) + 1 * TILE_BYTES + aoff);                 \
            }                                                                  \
            _Pragma("unroll")                                                  \
            for (int np = 0; np < 4; np++) {                                   \
                uint32_t boff = (uint32_t)(warp_n * 64 + np * 16 +             \
                                           ((lane >> 4) << 3) + (lane & 7)) * GP_BYTES \
                              + ks * 32 + ((lane >> 3) & 1) * 16;              \
                uint32_t bh[4], bl[4];                                         \
                ldsm4(bh, (base) + 2 * TILE_BYTES + boff);                     \
                ldsm4(bl, (base) + 3 * TILE_BYTES + boff);                     \
                MMAOP(acc[0][2 * np],     ah[0], bh[0], bh[1]);                \
                MMAOP(acc[0][2 * np + 1], ah[0], bh[2], bh[3]);                \
                MMAOP(acc[1][2 * np],     ah[1], bh[0], bh[1]);                \
                MMAOP(acc[1][2 * np + 1], ah[1], bh[2], bh[3]);                \
                MMAOP(acc[0][2 * np],     ah[0], bl[0], bl[1]);                \
                MMAOP(acc[0][2 * np + 1], ah[0], bl[2], bl[3]);                \
                MMAOP(acc[1][2 * np],     ah[1], bl[0], bl[1]);                \
                MMAOP(acc[1][2 * np + 1], ah[1], bl[2], bl[3]);                \
                MMAOP(acc[0][2 * np],     al[0], bh[0], bh[1]);                \
                MMAOP(acc[0][2 * np + 1], al[0], bh[2], bh[3]);                \
                MMAOP(acc[1][2 * np],     al[1], bh[0], bh[1]);                \
                MMAOP(acc[1][2 * np + 1], al[1], bh[2], bh[3]);                \
            }                                                                  \
        }                                                                      \
    }

// fp16 2-stream MMA: A single-word, B hi/lo pair (tiles 0,1,2).
#define MMA_CHUNK2S(base)                                                      \
    {                                                                          \
        _Pragma("unroll")                                                      \
        for (int ks = 0; ks < 2; ks++) {                                       \
            uint32_t ah[2][4];                                                 \
            _Pragma("unroll")                                                  \
            for (int wm = 0; wm < 2; wm++) {                                   \
                uint32_t aoff = (uint32_t)(warp_m * 32 + wm * 16 + (lane & 15)) * GP_BYTES \
                              + ks * 32 + (lane >> 4) * 16;                    \
                ldsm4(ah[wm], (base) + 0 * TILE_BYTES + aoff);                 \
            }                                                                  \
            _Pragma("unroll")                                                  \
            for (int np = 0; np < 4; np++) {                                   \
                uint32_t boff = (uint32_t)(warp_n * 64 + np * 16 +             \
                                           ((lane >> 4) << 3) + (lane & 7)) * GP_BYTES \
                              + ks * 32 + ((lane >> 3) & 1) * 16;              \
                uint32_t bh[4], bl[4];                                         \
                ldsm4(bh, (base) + 1 * TILE_BYTES + boff);                     \
                ldsm4(bl, (base) + 2 * TILE_BYTES + boff);                     \
                mma_hf(acc[0][2 * np],     ah[0], bh[0], bh[1]);               \
                mma_hf(acc[0][2 * np + 1], ah[0], bh[2], bh[3]);               \
                mma_hf(acc[1][2 * np],     ah[1], bh[0], bh[1]);               \
                mma_hf(acc[1][2 * np + 1], ah[1], bh[2], bh[3]);               \
                mma_hf(acc[0][2 * np],     ah[0], bl[0], bl[1]);               \
                mma_hf(acc[0][2 * np + 1], ah[0], bl[2], bl[3]);               \
                mma_hf(acc[1][2 * np],     ah[1], bl[0], bl[1]);               \
                mma_hf(acc[1][2 * np + 1], ah[1], bl[2], bl[3]);               \
            }                                                                  \
        }                                                                      \
    }

// fp16 1-stream MMA: A single x B single (tiles 0,1).
#define MMA_CHUNK1S(base)                                                      \
    {                                                                          \
        _Pragma("unroll")                                                      \
        for (int ks = 0; ks < 2; ks++) {                                       \
            uint32_t ah[2][4];                                                 \
            _Pragma("unroll")                                                  \
            for (int wm = 0; wm < 2; wm++) {                                   \
                uint32_t aoff = (uint32_t)(warp_m * 32 + wm * 16 + (lane & 15)) * GP_BYTES \
                              + ks * 32 + (lane >> 4) * 16;                    \
                ldsm4(ah[wm], (base) + 0 * TILE_BYTES + aoff);                 \
            }                                                                  \
            _Pragma("unroll")                                                  \
            for (int np = 0; np < 4; np++) {                                   \
                uint32_t boff = (uint32_t)(warp_n * 64 + np * 16 +             \
                                           ((lane >> 4) << 3) + (lane & 7)) * GP_BYTES \
                              + ks * 32 + ((lane >> 3) & 1) * 16;              \
                uint32_t bh[4];                                                \
                ldsm4(bh, (base) + 1 * TILE_BYTES + boff);                     \
                mma_hf(acc[0][2 * np],     ah[0], bh[0], bh[1]);               \
                mma_hf(acc[0][2 * np + 1], ah[0], bh[2], bh[3]);               \
                mma_hf(acc[1][2 * np],     ah[1], bh[0], bh[1]);               \
                mma_hf(acc[1][2 * np + 1], ah[1], bh[2], bh[3]);               \
            }                                                                  \
        }                                                                      \
    }

// ---------------------------------------------------------------------------
// Kernel 1: projection GEMM, fp16 3-stream (x pair . W pair, K = 512).
// Epilogue: theta fp16 single, phi fp16 single, g fp32.
// ---------------------------------------------------------------------------
__global__ __launch_bounds__(256, 2) void projmma_kernel(
    const float* __restrict__ b_theta, const float* __restrict__ b_phi,
    const float* __restrict__ b_g)
{
    extern __shared__ char sm[];
    const uint32_t sb = smem_u32(sm);
    const int t = threadIdx.x, lane = t & 31, wid = t >> 5;
    const int warp_m = wid >> 1, warp_n = wid & 1;
    const int m0 = blockIdx.x * 128, j0 = blockIdx.y * 128;

    float acc[2][8][4];
    #pragma unroll
    for (int i = 0; i < 2; i++)
        #pragma unroll
        for (int j = 0; j < 8; j++)
            #pragma unroll
            for (int k = 0; k < 4; k++) acc[i][j][k] = 0.0f;

    const int lr  = t >> 2;
    const int seg = t & 3;

    LOAD_CHUNK4(sb, g_xh, g_xl, g_wh, g_wl, C_, C_, m0, j0, 0);
    CP_COMMIT();

    const int NCH = C_ / KCHUNK;   // 16
    for (int kc = 0; kc < NCH; kc++) {
        const int buf = kc & 1;
        if (kc + 1 < NCH) {
            LOAD_CHUNK4(sb + (buf ^ 1) * BUF4_BYTES, g_xh, g_xl, g_wh, g_wl,
                        C_, C_, m0, j0, (kc + 1) * KCHUNK);
            CP_COMMIT();
            CP_WAIT1();
        } else {
            CP_WAIT0();
        }
        __syncthreads();
        MMA_CHUNK3S(sb + buf * BUF4_BYTES, mma_hf);
        __syncthreads();
    }

    const int sel = j0 >> 8;
    const float* __restrict__ bias =
        (sel == 0) ? b_theta : (sel == 1) ? b_phi : b_g;

    #pragma unroll
    for (int wm = 0; wm < 2; wm++) {
        #pragma unroll
        for (int h = 0; h < 2; h++) {
            int row = m0 + warp_m * 32 + wm * 16 + (lane >> 2) + h * 8;
            #pragma unroll
            for (int nt = 0; nt < 8; nt++) {
                int col = j0 + warp_n * 64 + nt * 8 + (lane & 3) * 2;
                int jj  = col & 255;
                float v0 = acc[wm][nt][2 * h]     + bias[jj];
                float v1 = acc[wm][nt][2 * h + 1] + bias[jj + 1];
                size_t di = (size_t)row * 256 + jj;
                if (sel == 2) {
                    float2 f2; f2.x = v0; f2.y = v1;
                    *(float2*)&g_gv[di] = f2;
                } else if (sel == 0) {
                    *(uint32_t*)&g_th[di] = pack_hf(v0, v1);
                } else {
                    *(uint32_t*)&g_fh[di] = pack_hf(v0, v1);
                }
            }
        }
    }
}

// ---------------------------------------------------------------------------
// Kernel 3: transpose + split g: [b][k][o] fp32 -> gT bf16 hi/lo [b][o][k].
// ---------------------------------------------------------------------------
__global__ __launch_bounds__(256) void tsplit_kernel()
{
    __shared__ float tile[32][33];
    const int b  = blockIdx.z;
    const int k0 = blockIdx.x * 32;
    const int o0 = blockIdx.y * 32;
    const int tx = threadIdx.x & 31;
    const int ty = threadIdx.x >> 5;

    #pragma unroll
    for (int jj = 0; jj < 4; jj++) {
        int k = k0 + ty + 8 * jj;
        tile[ty + 8 * jj][tx] = g_gv[(size_t)(b * N_ + k) * 256 + o0 + tx];
    }
    __syncthreads();
    #pragma unroll
    for (int jj = 0; jj < 4; jj++) {
        int o = o0 + ty + 8 * jj;
        float v = tile[tx][ty + 8 * jj];
        float h = __bfloat162float(__float2bfloat16(v));
        size_t di = (size_t)(b * 256 + o) * N_ + k0 + tx;
        g_gTh[di] = __float2bfloat16(h);
        g_gTl[di] = __float2bfloat16(v - h);
    }
}

// ---------------------------------------------------------------------------
// Kernel 4: GEMM-A (fp16 1-stream: theta single . phi single) + fused exp.
// ---------------------------------------------------------------------------
__global__ __launch_bounds__(256, 2) void gemmA_kernel()
{
    extern __shared__ char sm[];
    const uint32_t sb = smem_u32(sm);
    const int t = threadIdx.x, lane = t & 31, wid = t >> 5;
    const int warp_m = wid >> 1, warp_n = wid & 1;
    const int m0 = blockIdx.x * 128, n0 = blockIdx.y * 128, b = blockIdx.z;

    float acc[2][8][4];
    #pragma unroll
    for (int i = 0; i < 2; i++)
        #pragma unroll
        for (int j = 0; j < 8; j++)
            #pragma unroll
            for (int k = 0; k < 4; k++) acc[i][j][k] = 0.0f;

    const int lr  = t >> 2;
    const int seg = t & 3;
    const int rA = b * N_ + m0, rB = b * N_ + n0;

    LOAD_CHUNK2(sb, g_th, g_fh, 256, 256, rA, rB, 0);
    CP_COMMIT();

    const int NCH = 256 / KCHUNK;   // 8
    for (int kc = 0; kc < NCH; kc++) {
        const int buf = kc & 1;
        if (kc + 1 < NCH) {
            LOAD_CHUNK2(sb + (buf ^ 1) * BUF2_BYTES, g_th, g_fh,
                        256, 256, rA, rB, (kc + 1) * KCHUNK);
            CP_COMMIT();
            CP_WAIT1();
        } else {
            CP_WAIT0();
        }
        __syncthreads();
        MMA_CHUNK1S(sb + buf * BUF2_BYTES);
        __syncthreads();
    }

    // fused exp epilogue
    #pragma unroll
    for (int wm = 0; wm < 2; wm++) {
        #pragma unroll
        for (int h = 0; h < 2; h++) {
            int row = m0 + warp_m * 32 + wm * 16 + (lane >> 2) + h * 8;
            __nv_bfloat16* __restrict__ PH =
                &g_ph[(size_t)(b * N_ + row) * N_ + n0 + warp_n * 64];
            __nv_bfloat16* __restrict__ PL =
                &g_pl[(size_t)(b * N_ + row) * N_ + n0 + warp_n * 64];
            float lsum = 0.0f;
            #pragma unroll
            for (int nt = 0; nt < 8; nt++) {
                float p0 = __expf(acc[wm][nt][2 * h]     - EXP_SHIFT);
                float p1 = __expf(acc[wm][nt][2 * h + 1] - EXP_SHIFT);
                lsum += p0 + p1;
                float h0 = __bfloat162float(__float2bfloat16(p0));
                float h1 = __bfloat162float(__float2bfloat16(p1));
                *(uint32_t*)&PH[nt * 8 + (lane & 3) * 2] = pack_bf(h0, h1);
                *(uint32_t*)&PL[nt * 8 + (lane & 3) * 2] = pack_bf(p0 - h0, p1 - h1);
            }
            lsum += __shfl_xor_sync(0xffffffffu, lsum, 1);
            lsum += __shfl_xor_sync(0xffffffffu, lsum, 2);
            if ((lane & 3) == 0)
                g_lpart[(size_t)(b * N_ + row) * 64 + blockIdx.y * 2 + warp_n] = lsum;
        }
    }
}

// ---------------------------------------------------------------------------
// Kernel 5: reduce row-sum partials -> 1/l.
// ---------------------------------------------------------------------------
__global__ __launch_bounds__(256) void lsum_kernel()
{
    const int w = threadIdx.x >> 5, lane = threadIdx.x & 31;
    const int gr = blockIdx.x * 8 + w;
    float s = g_lpart[(size_t)gr * 64 + lane] + g_lpart[(size_t)gr * 64 + lane + 32];
    #pragma unroll
    for (int off = 16; off > 0; off >>= 1)
        s += __shfl_xor_sync(0xffffffffu, s, off);
    if (lane == 0) g_rinv[gr] = 1.0f / s;
}

// ---------------------------------------------------------------------------
// Kernel 6: GEMM-C (bf16 3-stream). Y = P . gT (K = 4096); y -> fp16 single.
// ---------------------------------------------------------------------------
__global__ __launch_bounds__(256, 2) void gemmC_kernel()
{
    extern __shared__ char sm[];
    const uint32_t sb = smem_u32(sm);
    const int t = threadIdx.x, lane = t & 31, wid = t >> 5;
    const int warp_m = wid >> 1, warp_n = wid & 1;
    const int m0 = blockIdx.x * 128, n0 = blockIdx.y * 128, b = blockIdx.z;

    float acc[2][8][4];
    #pragma unroll
    for (int i = 0; i < 2; i++)
        #pragma unroll
        for (int j = 0; j < 8; j++)
            #pragma unroll
            for (int k = 0; k < 4; k++) acc[i][j][k] = 0.0f;

    const int lr  = t >> 2;
    const int seg = t & 3;
    const int rA = b * N_ + m0, rB = b * 256 + n0;

    LOAD_CHUNK4(sb, g_ph, g_pl, g_gTh, g_gTl, (size_t)N_, (size_t)N_, rA, rB, 0);
    CP_COMMIT();

    const int NCH = N_ / KCHUNK;   // 128
    for (int kc = 0; kc < NCH; kc++) {
        const int buf = kc & 1;
        if (kc + 1 < NCH) {
            LOAD_CHUNK4(sb + (buf ^ 1) * BUF4_BYTES, g_ph, g_pl, g_gTh, g_gTl,
                        (size_t)N_, (size_t)N_, rA, rB, (kc + 1) * KCHUNK);
            CP_COMMIT();
            CP_WAIT1();
        } else {
            CP_WAIT0();
        }
        __syncthreads();
        MMA_CHUNK3S(sb + buf * BUF4_BYTES, mma_bf);
        __syncthreads();
    }

    #pragma unroll
    for (int wm = 0; wm < 2; wm++) {
        #pragma unroll
        for (int h = 0; h < 2; h++) {
            int row = m0 + warp_m * 32 + wm * 16 + (lane >> 2) + h * 8;
            float ri = g_rinv[b * N_ + row];
            size_t dbase = (size_t)(b * N_ + row) * 256 + n0 + warp_n * 64;
            #pragma unroll
            for (int nt = 0; nt < 8; nt++) {
                float v0 = acc[wm][nt][2 * h]     * ri;
                float v1 = acc[wm][nt][2 * h + 1] * ri;
                size_t di = dbase + nt * 8 + (lane & 3) * 2;
                *(uint32_t*)&g_yh[di] = pack_hf(v0, v1);
            }
        }
    }
}

// ---------------------------------------------------------------------------
// Kernel 7: output projection (fp16 2-stream: y single . w_out pair)
// + bias + residual. K = 256.
// ---------------------------------------------------------------------------
__global__ __launch_bounds__(256, 2) void outprojmma_kernel(
    const float* __restrict__ x, const float* __restrict__ b_out,
    float* __restrict__ out)
{
    extern __shared__ char sm[];
    const uint32_t sb = smem_u32(sm);
    const int t = threadIdx.x, lane = t & 31, wid = t >> 5;
    const int warp_m = wid >> 1, warp_n = wid & 1;
    const int m0 = blockIdx.x * 128, j0 = blockIdx.y * 128;

    float acc[2][8][4];
    #pragma unroll
    for (int i = 0; i < 2; i++)
        #pragma unroll
        for (int j = 0; j < 8; j++)
            #pragma unroll
            for (int k = 0; k < 4; k++) acc[i][j][k] = 0.0f;

    const int lr  = t >> 2;
    const int seg = t & 3;

    LOAD_CHUNK3(sb, g_yh, g_woh, g_wol, 256, 256, m0, j0, 0);
    CP_COMMIT();

    const int NCH = 256 / KCHUNK;   // 8
    for (int kc = 0; kc < NCH; kc++) {
        const int buf = kc & 1;
        if (kc + 1 < NCH) {
            LOAD_CHUNK3(sb + (buf ^ 1) * BUF3_BYTES, g_yh, g_woh, g_wol,
                        256, 256, m0, j0, (kc + 1) * KCHUNK);
            CP_COMMIT();
            CP_WAIT1();
        } else {
            CP_WAIT0();
        }
        __syncthreads();
        MMA_CHUNK2S(sb + buf * BUF3_BYTES);
        __syncthreads();
    }

    // stage transposed tile: smemT[c_local][n_local], pitch 132 floats.
    // 128*132*4 = 67584 <= 81920 (SMEM4 alloc).
    float* smemT = (float*)sm;
    #pragma unroll
    for (int wm = 0; wm < 2; wm++) {
        #pragma unroll
        for (int h = 0; h < 2; h++) {
            int row_l = warp_m * 32 + wm * 16 + (lane >> 2) + h * 8;
            #pragma unroll
            for (int nt = 0; nt < 8; nt++) {
                int col_l = warp_n * 64 + nt * 8 + (lane & 3) * 2;
                smemT[col_l * 132 + row_l]       = acc[wm][nt][2 * h];
                smemT[(col_l + 1) * 132 + row_l] = acc[wm][nt][2 * h + 1];
            }
        }
    }
    __syncthreads();

    const int b   = m0 >> 12;
    const int nn0 = m0 & 4095;
    const int c_l  = t & 127;
    const int half = t >> 7;
    const int c = j0 + c_l;
    const float bo = b_out[c];
    const size_t obase = (size_t)(b * 512 + c) * 4096 + nn0 + half * 64;
    const float* sp = &smemT[c_l * 132 + half * 64];
    #pragma unroll
    for (int i = 0; i < 16; i++) {
        float4 xv = *(const float4*)&x[obase + i * 4];
        float4 o4;
        o4.x = sp[i * 4 + 0] + bo + xv.x;
        o4.y = sp[i * 4 + 1] + bo + xv.y;
        o4.z = sp[i * 4 + 2] + bo + xv.z;
        o4.w = sp[i * 4 + 3] + bo + xv.w;
        *(float4*)&out[obase + i * 4] = o4;
    }
}

// ---------------------------------------------------------------------------
extern "C" void kernel_launch(void* const* d_in, const int* in_sizes, int n_in,
                              void* d_out, int out_size)
{
    (void)in_sizes; (void)n_in; (void)out_size;
    const float* x       = (const float*)d_in[0];
    const float* w_theta = (const float*)d_in[1];
    const float* b_theta = (const float*)d_in[2];
    const float* w_phi   = (const float*)d_in[3];
    const float* b_phi   = (const float*)d_in[4];
    const float* w_g     = (const float*)d_in[5];
    const float* b_g     = (const float*)d_in[6];
    const float* w_out   = (const float*)d_in[7];
    const float* b_out   = (const float*)d_in[8];
    float* out = (float*)d_out;

    xtsplit_kernel<<<dim3(N_ / 32, C_ / 32, NB), 256>>>(x);
    wsplit_kernel<<<(3 * CI_ * C_ / 4) / 256, 256>>>(w_theta, w_phi, w_g);
    wosplit_kernel<<<(C_ * CI_ / 4) / 256, 256>>>(w_out);

    cudaFuncSetAttribute(projmma_kernel,
                         cudaFuncAttributeMaxDynamicSharedMemorySize, SMEM4);
    projmma_kernel<<<dim3(BN_ / 128, 6, 1), 256, SMEM4>>>(b_theta, b_phi, b_g);

    tsplit_kernel<<<dim3(N_ / 32, CI_ / 32, NB), 256>>>();

    cudaFuncSetAttribute(gemmA_kernel,
                         cudaFuncAttributeMaxDynamicSharedMemorySize, SMEM2);
    gemmA_kernel<<<dim3(N_ / 128, N_ / 128, NB), 256, SMEM2>>>();

    lsum_kernel<<<BN_ / 8, 256>>>();

    cudaFuncSetAttribute(gemmC_kernel,
                         cudaFuncAttributeMaxDynamicSharedMemorySize, SMEM4);
    gemmC_kernel<<<dim3(N_ / 128, CI_ / 128, NB), 256, SMEM4>>>();

    cudaFuncSetAttribute(outprojmma_kernel,
                         cudaFuncAttributeMaxDynamicSharedMemorySize, SMEM4);
    outprojmma_kernel<<<dim3(BN_ / 128, C_ / 128, 1), 256, SMEM4>>>(x, b_out, out);
}